// round 13
// baseline (speedup 1.0000x reference)
#include <cuda_runtime.h>
#include <cuda_bf16.h>
#include <cuda_fp16.h>
#include <cstdint>

#define SEQ    2048
#define DMODEL 1024
#define HDIM   64
#define MROWS  4096
#define BHCNT  32
#define WPR    512   // packed 2-elem words per dmodel row
#define LOG2E  1.4426950408889634f

// ---------------- device scratch (allocation-free rule) ----------------
__device__ uint32_t g_xhi[MROWS*WPR], g_xlo[MROWS*WPR];
__device__ uint32_t g_wqh[DMODEL*WPR], g_wql[DMODEL*WPR];
__device__ uint32_t g_wkh[DMODEL*WPR], g_wkl[DMODEL*WPR];
__device__ uint32_t g_wvh[DMODEL*WPR], g_wvl[DMODEL*WPR];
__device__ uint32_t g_woh[DMODEL*WPR], g_wol[DMODEL*WPR];
__device__ uint32_t g_qh [MROWS*WPR], g_ql [MROWS*WPR];
__device__ uint32_t g_kh [MROWS*WPR], g_kl [MROWS*WPR];
__device__ float    g_v  [MROWS*DMODEL];
__device__ uint32_t g_vth[BHCNT*32*64*32], g_vtl[BHCNT*32*64*32];
__device__ uint32_t g_ah [MROWS*WPR], g_al [MROWS*WPR];

// ---------------- helpers ----------------
__device__ __forceinline__ uint32_t smem_u32(const void* p) {
    uint32_t a;
    asm("{ .reg .u64 t; cvta.to.shared.u64 t, %1; cvt.u32.u64 %0, t; }" : "=r"(a) : "l"(p));
    return a;
}
__device__ __forceinline__ void cp_async16(uint32_t s, const void* g) {
    asm volatile("cp.async.cg.shared.global [%0], [%1], 16;" ::"r"(s), "l"(g) : "memory");
}
#define CP_COMMIT() asm volatile("cp.async.commit_group;" ::: "memory")
#define CP_WAIT(n)  asm volatile("cp.async.wait_group %0;" ::"n"(n) : "memory")

__device__ __forceinline__ void ldsm_x4(uint32_t& r0, uint32_t& r1, uint32_t& r2, uint32_t& r3,
                                        uint32_t addr) {
    asm volatile("ldmatrix.sync.aligned.m8n8.x4.shared.b16 {%0,%1,%2,%3}, [%4];"
                 : "=r"(r0), "=r"(r1), "=r"(r2), "=r"(r3) : "r"(addr));
}

// bf16 split (even elem in low half)
__device__ __forceinline__ void split2(float f0, float f1, uint32_t& hw, uint32_t& lw) {
    __nv_bfloat16 h0 = __float2bfloat16(f0), h1 = __float2bfloat16(f1);
    float r0 = f0 - __bfloat162float(h0);
    float r1 = f1 - __bfloat162float(h1);
    __nv_bfloat16 e0 = __float2bfloat16(r0), e1 = __float2bfloat16(r1);
    hw = (uint32_t)__bfloat16_as_ushort(h0) | ((uint32_t)__bfloat16_as_ushort(h1) << 16);
    lw = (uint32_t)__bfloat16_as_ushort(e0) | ((uint32_t)__bfloat16_as_ushort(e1) << 16);
}
// fp16 split (even elem in low half)
__device__ __forceinline__ void split2h(float f0, float f1, uint32_t& hw, uint32_t& lw) {
    __half h0 = __float2half_rn(f0), h1 = __float2half_rn(f1);
    float r0 = f0 - __half2float(h0);
    float r1 = f1 - __half2float(h1);
    __half2 hp = __halves2half2(h0, h1);
    __half2 lp = __halves2half2(__float2half_rn(r0), __float2half_rn(r1));
    hw = *(uint32_t*)&hp;
    lw = *(uint32_t*)&lp;
}
// exp2 of a float pair in fp16x2, returns packed half2 bits
__device__ __forceinline__ uint32_t exp2_h2(float a, float b) {
    __half2 h = h2exp2(__floats2half2_rn(a, b));
    return *(uint32_t*)&h;
}
__device__ __forceinline__ void mma_bf16(float* c, const uint32_t* a, const uint32_t* b) {
    asm volatile(
        "mma.sync.aligned.m16n8k16.row.col.f32.bf16.bf16.f32 "
        "{%0,%1,%2,%3}, {%4,%5,%6,%7}, {%8,%9}, {%0,%1,%2,%3};"
        : "+f"(c[0]), "+f"(c[1]), "+f"(c[2]), "+f"(c[3])
        : "r"(a[0]), "r"(a[1]), "r"(a[2]), "r"(a[3]), "r"(b[0]), "r"(b[1]));
}
__device__ __forceinline__ void mma_f16(float* c, const uint32_t* a, const uint32_t* b) {
    asm volatile(
        "mma.sync.aligned.m16n8k16.row.col.f32.f16.f16.f32 "
        "{%0,%1,%2,%3}, {%4,%5,%6,%7}, {%8,%9}, {%0,%1,%2,%3};"
        : "+f"(c[0]), "+f"(c[1]), "+f"(c[2]), "+f"(c[3])
        : "r"(a[0]), "r"(a[1]), "r"(a[2]), "r"(a[3]), "r"(b[0]), "r"(b[1]));
}

// ---------------- pre-split pass ----------------
__global__ void __launch_bounds__(256) split_all_kernel(const float* __restrict__ X,
                                                        const float* __restrict__ Wq,
                                                        const float* __restrict__ Wk,
                                                        const float* __restrict__ Wv,
                                                        const float* __restrict__ Wo)
{
    const int i = blockIdx.x * 256 + threadIdx.x;
    const int NX = MROWS * WPR;
    const int NW = DMODEL * WPR;
    uint32_t h, l;
    if (i < NX) {
        float2 v = ((const float2*)X)[i];
        split2(v.x, v.y, h, l);
        g_xhi[i] = h; g_xlo[i] = l;
    } else {
        int t = i - NX;
        int sel = t >> 19, idx = t & (NW - 1);
        const float* src; uint32_t *dh, *dl;
        if      (sel == 0) { src = Wq; dh = g_wqh; dl = g_wql; }
        else if (sel == 1) { src = Wk; dh = g_wkh; dl = g_wkl; }
        else if (sel == 2) { src = Wv; dh = g_wvh; dl = g_wvl; }
        else               { src = Wo; dh = g_woh; dl = g_wol; }
        float2 v = ((const float2*)src)[idx];
        split2(v.x, v.y, h, l);
        dh[idx] = h; dl[idx] = l;
    }
}

// ---------------- V transpose + fp16-split pre-pass ----------------
__global__ void __launch_bounds__(256) vtrans_kernel()
{
    __shared__ float vs[64 * 65];
    const int j = blockIdx.x, bh = blockIdx.y;
    const int tid = threadIdx.x;
    const float* src = g_v + (size_t)bh * (SEQ * HDIM) + (size_t)j * 64 * HDIM;
#pragma unroll
    for (int it = 0; it < 16; it++) {
        const int i = tid + it * 256;
        const int kv = i >> 6, hd = i & 63;
        vs[kv * 65 + hd] = src[kv * 64 + hd];
    }
    __syncthreads();
    const size_t obase = ((size_t)bh * 32 + j) * 2048;
#pragma unroll
    for (int it = 0; it < 8; it++) {
        const int i = tid + it * 256;
        const int hd = i >> 5, w = i & 31;
        uint32_t h, l;
        split2h(vs[(2 * w) * 65 + hd], vs[(2 * w + 1) * 65 + hd], h, l);
        g_vth[obase + hd * 32 + w] = h;
        g_vtl[obase + hd * 32 + w] = l;
    }
}

// ---------------- bf16-split GEMM: 512 thr, 128x256 tile, BK=64, 2-stage ----------------
#define GSTGW 24576
#define GEMM_SMEM (2 * GSTGW * 4)   // 192KB

__device__ __forceinline__ void gemm_body(const uint32_t* __restrict__ Ah,
                                          const uint32_t* __restrict__ Al,
                                          const uint32_t* __restrict__ Bh,
                                          const uint32_t* __restrict__ Bl,
                                          int mode, float oscale,
                                          float* __restrict__ Cf,
                                          uint32_t* __restrict__ OH,
                                          uint32_t* __restrict__ OL,
                                          const float* __restrict__ bias)
{
    extern __shared__ uint32_t sm[];
    const uint32_t smu = smem_u32(sm);
    const int tid = threadIdx.x;
    const int wid = tid >> 5, lane = tid & 31;
    const int gr = lane >> 2, tg = lane & 3;
    const int m0 = blockIdx.y * 128, n0 = blockIdx.x * 256;
    const int wm = (wid >> 2) * 32, wn = (wid & 3) * 64;

    const int la = lane & 15;
    const int ajbit = lane >> 4;
    const int lb = lane & 7;
    const int bjbit = (lane >> 3) & 1;
    const int bplane = lane >> 4;
    const uint32_t aRow = (uint32_t)(wm + la) * 128;
    const uint32_t bRow = 32768u + (uint32_t)bplane * 32768u + (uint32_t)(wn + lb) * 128;
    const int la7 = la & 7;

    float acc[2][8][4];
#pragma unroll
    for (int i = 0; i < 2; i++)
#pragma unroll
        for (int j = 0; j < 8; j++)
#pragma unroll
            for (int c = 0; c < 4; c++) acc[i][j][c] = 0.f;

    auto load_stage = [&](int kt, int stg) {
        const uint32_t sb = smu + stg * GSTGW * 4;
#pragma unroll
        for (int it = 0; it < 12; it++) {
            const int c = tid + it * 512;
            const uint32_t* src;
            uint32_t wordoff;
            if (c < 2048) {
                const int r = (c >> 3) & 127, jj = c & 7;
                wordoff = ((c >> 10) ? 4096u : 0u) + r * 32 + ((jj ^ (r & 7)) << 2);
                src = ((c >> 10) ? Al : Ah) + (size_t)(m0 + r) * WPR + kt * 32 + jj * 4;
            } else {
                const int cb = c - 2048;
                const int r = (cb >> 3) & 255, jj = cb & 7;
                wordoff = ((cb >> 11) ? 16384u : 8192u) + r * 32 + ((jj ^ (r & 7)) << 2);
                src = ((cb >> 11) ? Bl : Bh) + (size_t)(n0 + r) * WPR + kt * 32 + jj * 4;
            }
            cp_async16(sb + wordoff * 4, src);
        }
    };

    load_stage(0, 0); CP_COMMIT();
    load_stage(1, 1); CP_COMMIT();

    for (int kt = 0; kt < 16; kt++) {
        CP_WAIT(1);
        __syncthreads();
        const uint32_t stageB = smu + (kt & 1) * GSTGW * 4;
#pragma unroll
        for (int kc = 0; kc < 4; kc++) {
            const uint32_t aswz = (uint32_t)(((2 * kc + ajbit) ^ la7) << 4);
            const uint32_t bswz = (uint32_t)(((2 * kc + bjbit) ^ lb) << 4);
            uint32_t ah[2][4], al[2][4];
#pragma unroll
            for (int mi = 0; mi < 2; mi++) {
                const uint32_t abase = stageB + aRow + mi * 2048 + aswz;
                ldsm_x4(ah[mi][0], ah[mi][1], ah[mi][2], ah[mi][3], abase);
                ldsm_x4(al[mi][0], al[mi][1], al[mi][2], al[mi][3], abase + 16384);
            }
#pragma unroll
            for (int njb = 0; njb < 2; njb++) {
                uint32_t bf[4][4];
#pragma unroll
                for (int q = 0; q < 4; q++)
                    ldsm_x4(bf[q][0], bf[q][1], bf[q][2], bf[q][3],
                            stageB + bRow + (njb * 4 + q) * 1024 + bswz);
#pragma unroll
                for (int q = 0; q < 4; q++)
#pragma unroll
                    for (int mi = 0; mi < 2; mi++)
                        mma_bf16(acc[mi][njb * 4 + q], ah[mi], &bf[q][0]);
#pragma unroll
                for (int q = 0; q < 4; q++)
#pragma unroll
                    for (int mi = 0; mi < 2; mi++)
                        mma_bf16(acc[mi][njb * 4 + q], ah[mi], &bf[q][2]);
#pragma unroll
                for (int q = 0; q < 4; q++)
#pragma unroll
                    for (int mi = 0; mi < 2; mi++)
                        mma_bf16(acc[mi][njb * 4 + q], al[mi], &bf[q][0]);
            }
        }
        __syncthreads();
        if (kt + 2 < 16) load_stage(kt + 2, kt & 1);
        CP_COMMIT();
    }

#pragma unroll
    for (int mi = 0; mi < 2; mi++) {
        const int r0 = m0 + wm + mi * 16 + gr;
#pragma unroll
        for (int nj = 0; nj < 8; nj++) {
            const int c0 = n0 + wn + nj * 8 + 2 * tg;
            float v0 = acc[mi][nj][0], v1 = acc[mi][nj][1];
            float v2 = acc[mi][nj][2], v3 = acc[mi][nj][3];
            if (mode == 0) {
                v0 *= oscale; v1 *= oscale; v2 *= oscale; v3 *= oscale;
                uint32_t h, l;
                split2(v0, v1, h, l);
                OH[(size_t)r0 * WPR + (c0 >> 1)] = h;
                OL[(size_t)r0 * WPR + (c0 >> 1)] = l;
                split2(v2, v3, h, l);
                OH[(size_t)(r0 + 8) * WPR + (c0 >> 1)] = h;
                OL[(size_t)(r0 + 8) * WPR + (c0 >> 1)] = l;
            } else {
                if (mode == 2) {
                    const float b0 = bias[c0], b1 = bias[c0 + 1];
                    v0 += b0; v1 += b1; v2 += b0; v3 += b1;
                }
                *(float2*)(Cf + (size_t)r0 * DMODEL + c0) = make_float2(v0, v1);
                *(float2*)(Cf + (size_t)(r0 + 8) * DMODEL + c0) = make_float2(v2, v3);
            }
        }
    }
}

__global__ void __launch_bounds__(512) qkv_kernel()
{
    const int z = blockIdx.z;
    if (z == 0)      gemm_body(g_xhi, g_xlo, g_wqh, g_wql, 0, LOG2E, nullptr, g_qh, g_ql, nullptr);
    else if (z == 1) gemm_body(g_xhi, g_xlo, g_wkh, g_wkl, 0, 1.0f, nullptr, g_kh, g_kl, nullptr);
    else             gemm_body(g_xhi, g_xlo, g_wvh, g_wvl, 1, 1.0f, g_v, nullptr, nullptr, nullptr);
}

__global__ void __launch_bounds__(512) out_kernel(const float* __restrict__ bias,
                                                  float* __restrict__ out)
{
    gemm_body(g_ah, g_al, g_woh, g_wol, 2, 1.0f, out, nullptr, nullptr, bias);
}

// ---------------- tensor-core causal flash attention ----------------
// Q pre-scaled by log2e; exp via h2exp2 (fp16x2); row-sum via ones-MMA.
#define ATT_SMEM (3 * 8192 * 4)   // 96KB
#define ONES_H2 0x3C003C00u

__global__ void __launch_bounds__(256, 2) attn_kernel()
{
    extern __shared__ uint32_t sm[];
    const uint32_t smu = smem_u32(sm);
    const int tid = threadIdx.x;
    const int wid = tid >> 5, lane = tid & 31;
    const int gr = lane >> 2, tg = lane & 3;
    const int qi = 15 - blockIdx.x;
    const int bh = blockIdx.y;
    const int qbase = qi * 128;
    const size_t wbase = (size_t)bh * 65536;
    const size_t vtbase = (size_t)bh * 65536;

    const int lb = lane & 7;
    const int bjbit = (lane >> 3) & 1;
    const int bplane = lane >> 4;
    const uint32_t kRow = (uint32_t)bplane * 8192u + (uint32_t)lb * 128;
    const uint32_t vRow = 16384u + (uint32_t)bplane * 8192u + (uint32_t)lb * 128;

#pragma unroll
    for (int it = 0; it < 4; it++) {
        const int i = tid + it * 256;
        const int r = i >> 3, j = i & 7;
        const uint32_t dst = (r * 32 + ((j ^ (r & 7)) << 2)) * 4;
        cp_async16(smu + dst, g_qh + wbase + (size_t)(qbase + r) * 32 + j * 4);
        cp_async16(smu + (4096 * 4) + dst, g_ql + wbase + (size_t)(qbase + r) * 32 + j * 4);
    }
    CP_COMMIT(); CP_WAIT(0);
    __syncthreads();

    uint32_t qh[4][4], ql[4][4];
    {
        const int r = wid * 16 + gr;
#pragma unroll
        for (int kc = 0; kc < 4; kc++) {
            const int ch0 = ((2 * kc) ^ (r & 7)) << 2;
            const int ch1 = ((2 * kc + 1) ^ (r & 7)) << 2;
            qh[kc][0] = sm[r * 32 + ch0 + tg];
            qh[kc][1] = sm[(r + 8) * 32 + ch0 + tg];
            qh[kc][2] = sm[r * 32 + ch1 + tg];
            qh[kc][3] = sm[(r + 8) * 32 + ch1 + tg];
            ql[kc][0] = sm[4096 + r * 32 + ch0 + tg];
            ql[kc][1] = sm[4096 + (r + 8) * 32 + ch0 + tg];
            ql[kc][2] = sm[4096 + r * 32 + ch1 + tg];
            ql[kc][3] = sm[4096 + (r + 8) * 32 + ch1 + tg];
        }
    }
    __syncthreads();

    float m0 = -1e30f, m1 = -1e30f;
    float lacc[4] = {0.f, 0.f, 0.f, 0.f};   // ones-MMA row sums (c0,c1=row0; c2,c3=row1)
    float oacc[8][4];
#pragma unroll
    for (int nf = 0; nf < 8; nf++)
#pragma unroll
        for (int c = 0; c < 4; c++) oacc[nf][c] = 0.f;

    const int numj = 2 * qi + 2;

    auto load_kv = [&](int j, int st) {
        const uint32_t sb = smu + st * 8192 * 4;
#pragma unroll
        for (int it = 0; it < 8; it++) {
            const int c = tid + it * 256;
            const int part = c >> 9;
            const int r = (c >> 3) & 63;
            const int jj = c & 7;
            const uint32_t dst = sb + (part * 2048 + r * 32 + ((jj ^ (r & 7)) << 2)) * 4;
            const uint32_t* src;
            if      (part == 0) src = g_kh + wbase + (size_t)(j * 64 + r) * 32;
            else if (part == 1) src = g_kl + wbase + (size_t)(j * 64 + r) * 32;
            else if (part == 2) src = g_vth + vtbase + (size_t)j * 2048 + r * 32;
            else                src = g_vtl + vtbase + (size_t)j * 2048 + r * 32;
            cp_async16(dst, src + jj * 4);
        }
    };

    load_kv(0, 0); CP_COMMIT();
    if (numj > 1) load_kv(1, 1);
    CP_COMMIT();

    const uint32_t bones[2] = { ONES_H2, ONES_H2 };

    int st = 0, st2 = 2;
    for (int j = 0; j < numj; j++) {
        CP_WAIT(1);
        __syncthreads();
        if (j + 2 < numj) load_kv(j + 2, st2);
        CP_COMMIT();

        const uint32_t stageB = smu + st * 32768;
        const int kvb = j * 64;

        // ---- S' = (log2e * Q) K^T ----
        float s[8][4];
#pragma unroll
        for (int nf = 0; nf < 8; nf++)
#pragma unroll
            for (int c = 0; c < 4; c++) s[nf][c] = 0.f;
#pragma unroll
        for (int kc = 0; kc < 4; kc++) {
            const uint32_t bswz = (uint32_t)(((2 * kc + bjbit) ^ lb) << 4);
#pragma unroll
            for (int np = 0; np < 4; np++) {
                const int nf0 = 2 * np, nf1 = nf0 + 1;
                uint32_t k0[4], k1[4];
                ldsm_x4(k0[0], k0[1], k0[2], k0[3], stageB + kRow + nf0 * 1024 + bswz);
                ldsm_x4(k1[0], k1[1], k1[2], k1[3], stageB + kRow + nf1 * 1024 + bswz);
                mma_bf16(s[nf0], qh[kc], &k0[0]);
                mma_bf16(s[nf1], qh[kc], &k1[0]);
                mma_bf16(s[nf0], qh[kc], &k0[2]);
                mma_bf16(s[nf1], qh[kc], &k1[2]);
                mma_bf16(s[nf0], ql[kc], &k0[0]);
                mma_bf16(s[nf1], ql[kc], &k1[0]);
            }
        }

        if (j >= 2 * qi) {
            const int row0 = qbase + wid * 16 + gr, row1 = row0 + 8;
#pragma unroll
            for (int nf = 0; nf < 8; nf++) {
                const int col = kvb + nf * 8 + 2 * tg;
                if (col > row0)     s[nf][0] = -1e30f;
                if (col + 1 > row0) s[nf][1] = -1e30f;
                if (col > row1)     s[nf][2] = -1e30f;
                if (col + 1 > row1) s[nf][3] = -1e30f;
            }
        }

        // ---- row max (scaled domain) ----
        float rm0 = -1e30f, rm1 = -1e30f;
#pragma unroll
        for (int nf = 0; nf < 8; nf++) {
            rm0 = fmaxf(rm0, fmaxf(s[nf][0], s[nf][1]));
            rm1 = fmaxf(rm1, fmaxf(s[nf][2], s[nf][3]));
        }
        rm0 = fmaxf(rm0, __shfl_xor_sync(0xffffffffu, rm0, 1));
        rm0 = fmaxf(rm0, __shfl_xor_sync(0xffffffffu, rm0, 2));
        rm1 = fmaxf(rm1, __shfl_xor_sync(0xffffffffu, rm1, 1));
        rm1 = fmaxf(rm1, __shfl_xor_sync(0xffffffffu, rm1, 2));
        const float mn0 = fmaxf(m0, rm0), mn1 = fmaxf(m1, rm1);
        const float sc0 = exp2f(m0 - mn0), sc1 = exp2f(m1 - mn1);
        m0 = mn0; m1 = mn1;
#pragma unroll
        for (int nf = 0; nf < 8; nf++) {
            oacc[nf][0] *= sc0; oacc[nf][1] *= sc0;
            oacc[nf][2] *= sc1; oacc[nf][3] *= sc1;
        }
        lacc[0] *= sc0; lacc[1] *= sc0; lacc[2] *= sc1; lacc[3] *= sc1;

        // ---- P = exp2(s'-m') in fp16x2; l += P·1 (ones-MMA); O += P V ----
#pragma unroll
        for (int kc = 0; kc < 4; kc++) {
            const uint32_t bswz = (uint32_t)(((2 * kc + bjbit) ^ lb) << 4);
            uint32_t pa[4];
            pa[0] = exp2_h2(s[2 * kc][0] - mn0,     s[2 * kc][1] - mn0);
            pa[1] = exp2_h2(s[2 * kc][2] - mn1,     s[2 * kc][3] - mn1);
            pa[2] = exp2_h2(s[2 * kc + 1][0] - mn0, s[2 * kc + 1][1] - mn0);
            pa[3] = exp2_h2(s[2 * kc + 1][2] - mn1, s[2 * kc + 1][3] - mn1);
            mma_f16(lacc, pa, bones);
#pragma unroll
            for (int np = 0; np < 4; np++) {
                const int nf0 = 2 * np, nf1 = nf0 + 1;
                uint32_t v0[4], v1[4];
                ldsm_x4(v0[0], v0[1], v0[2], v0[3], stageB + vRow + nf0 * 1024 + bswz);
                ldsm_x4(v1[0], v1[1], v1[2], v1[3], stageB + vRow + nf1 * 1024 + bswz);
                mma_f16(oacc[nf0], pa, &v0[0]);
                mma_f16(oacc[nf1], pa, &v1[0]);
                mma_f16(oacc[nf0], pa, &v0[2]);
                mma_f16(oacc[nf1], pa, &v1[2]);
            }
        }

        st = (st == 2) ? 0 : st + 1;
        st2 = (st2 == 2) ? 0 : st2 + 1;
    }

    const float inv0 = 1.f / lacc[0], inv1 = 1.f / lacc[2];
    const int row0 = qbase + wid * 16 + gr;
#pragma unroll
    for (int nf = 0; nf < 8; nf++) {
        uint32_t h, l;
        split2(oacc[nf][0] * inv0, oacc[nf][1] * inv0, h, l);
        const int w = nf * 4 + tg;
        g_ah[wbase + (size_t)row0 * 32 + w] = h;
        g_al[wbase + (size_t)row0 * 32 + w] = l;
        split2(oacc[nf][2] * inv1, oacc[nf][3] * inv1, h, l);
        g_ah[wbase + (size_t)(row0 + 8) * 32 + w] = h;
        g_al[wbase + (size_t)(row0 + 8) * 32 + w] = l;
    }
}

// ---------------------------------------------------------------------------
extern "C" void kernel_launch(void* const* d_in, const int* in_sizes, int n_in,
                              void* d_out, int out_size)
{
    const float* X  = (const float*)d_in[0];
    const float* Wq = (const float*)d_in[1];
    const float* Wk = (const float*)d_in[2];
    const float* Wv = (const float*)d_in[3];
    const float* Wo = (const float*)d_in[4];
    const float* bo = (const float*)d_in[5];
    float* out = (float*)d_out;

    cudaFuncSetAttribute(qkv_kernel, cudaFuncAttributeMaxDynamicSharedMemorySize, GEMM_SMEM);
    cudaFuncSetAttribute(out_kernel, cudaFuncAttributeMaxDynamicSharedMemorySize, GEMM_SMEM);
    cudaFuncSetAttribute(attn_kernel, cudaFuncAttributeMaxDynamicSharedMemorySize, ATT_SMEM);

    const int total_words = MROWS * WPR + 4 * DMODEL * WPR;
    split_all_kernel<<<total_words / 256, 256>>>(X, Wq, Wk, Wv, Wo);
    qkv_kernel<<<dim3(DMODEL / 256, MROWS / 128, 3), 512, GEMM_SMEM>>>();
    vtrans_kernel<<<dim3(32, BHCNT), 256>>>();
    attn_kernel<<<dim3(16, BHCNT), 256, ATT_SMEM>>>();
    out_kernel<<<dim3(DMODEL / 256, MROWS / 128), 512, GEMM_SMEM>>>(bo, out);
}

// round 14
// speedup vs baseline: 1.0640x; 1.0640x over previous
#include <cuda_runtime.h>
#include <cuda_bf16.h>
#include <cuda_fp16.h>
#include <cstdint>

#define SEQ    2048
#define DMODEL 1024
#define HDIM   64
#define MROWS  4096
#define BHCNT  32
#define WPR    512   // packed 2-elem words per dmodel row
#define LOG2E  1.4426950408889634f

// ---------------- device scratch (allocation-free rule) ----------------
__device__ uint32_t g_xhi[MROWS*WPR], g_xlo[MROWS*WPR];
__device__ uint32_t g_wqh[DMODEL*WPR], g_wql[DMODEL*WPR];
__device__ uint32_t g_wkh[DMODEL*WPR], g_wkl[DMODEL*WPR];
__device__ uint32_t g_wvh[DMODEL*WPR], g_wvl[DMODEL*WPR];
__device__ uint32_t g_woh[DMODEL*WPR], g_wol[DMODEL*WPR];
__device__ uint32_t g_qh [MROWS*WPR], g_ql [MROWS*WPR];
__device__ uint32_t g_kh [MROWS*WPR], g_kl [MROWS*WPR];
__device__ float    g_v  [MROWS*DMODEL];
__device__ uint32_t g_vth[BHCNT*32*64*32];   // single-plane fp16 V^T
__device__ uint32_t g_ah [MROWS*WPR], g_al [MROWS*WPR];

// ---------------- helpers ----------------
__device__ __forceinline__ uint32_t smem_u32(const void* p) {
    uint32_t a;
    asm("{ .reg .u64 t; cvta.to.shared.u64 t, %1; cvt.u32.u64 %0, t; }" : "=r"(a) : "l"(p));
    return a;
}
__device__ __forceinline__ void cp_async16(uint32_t s, const void* g) {
    asm volatile("cp.async.cg.shared.global [%0], [%1], 16;" ::"r"(s), "l"(g) : "memory");
}
#define CP_COMMIT() asm volatile("cp.async.commit_group;" ::: "memory")
#define CP_WAIT(n)  asm volatile("cp.async.wait_group %0;" ::"n"(n) : "memory")

__device__ __forceinline__ void ldsm_x4(uint32_t& r0, uint32_t& r1, uint32_t& r2, uint32_t& r3,
                                        uint32_t addr) {
    asm volatile("ldmatrix.sync.aligned.m8n8.x4.shared.b16 {%0,%1,%2,%3}, [%4];"
                 : "=r"(r0), "=r"(r1), "=r"(r2), "=r"(r3) : "r"(addr));
}
__device__ __forceinline__ void ldsm_x2(uint32_t& r0, uint32_t& r1, uint32_t addr) {
    asm volatile("ldmatrix.sync.aligned.m8n8.x2.shared.b16 {%0,%1}, [%2];"
                 : "=r"(r0), "=r"(r1) : "r"(addr));
}

// bf16 split (even elem in low half)
__device__ __forceinline__ void split2(float f0, float f1, uint32_t& hw, uint32_t& lw) {
    __nv_bfloat16 h0 = __float2bfloat16(f0), h1 = __float2bfloat16(f1);
    float r0 = f0 - __bfloat162float(h0);
    float r1 = f1 - __bfloat162float(h1);
    __nv_bfloat16 e0 = __float2bfloat16(r0), e1 = __float2bfloat16(r1);
    hw = (uint32_t)__bfloat16_as_ushort(h0) | ((uint32_t)__bfloat16_as_ushort(h1) << 16);
    lw = (uint32_t)__bfloat16_as_ushort(e0) | ((uint32_t)__bfloat16_as_ushort(e1) << 16);
}
__device__ __forceinline__ uint32_t pack_h2f(float f0, float f1) {
    __half2 h = __floats2half2_rn(f0, f1);
    return *(uint32_t*)&h;
}
// exp2 of a float pair in fp16x2
__device__ __forceinline__ uint32_t exp2_h2(float a, float b) {
    __half2 h = h2exp2(__floats2half2_rn(a, b));
    return *(uint32_t*)&h;
}
__device__ __forceinline__ void mma_bf16(float* c, const uint32_t* a, const uint32_t* b) {
    asm volatile(
        "mma.sync.aligned.m16n8k16.row.col.f32.bf16.bf16.f32 "
        "{%0,%1,%2,%3}, {%4,%5,%6,%7}, {%8,%9}, {%0,%1,%2,%3};"
        : "+f"(c[0]), "+f"(c[1]), "+f"(c[2]), "+f"(c[3])
        : "r"(a[0]), "r"(a[1]), "r"(a[2]), "r"(a[3]), "r"(b[0]), "r"(b[1]));
}
__device__ __forceinline__ void mma_f16(float* c, const uint32_t* a, const uint32_t* b) {
    asm volatile(
        "mma.sync.aligned.m16n8k16.row.col.f32.f16.f16.f32 "
        "{%0,%1,%2,%3}, {%4,%5,%6,%7}, {%8,%9}, {%0,%1,%2,%3};"
        : "+f"(c[0]), "+f"(c[1]), "+f"(c[2]), "+f"(c[3])
        : "r"(a[0]), "r"(a[1]), "r"(a[2]), "r"(a[3]), "r"(b[0]), "r"(b[1]));
}

// ---------------- pre-split pass ----------------
__global__ void __launch_bounds__(256) split_all_kernel(const float* __restrict__ X,
                                                        const float* __restrict__ Wq,
                                                        const float* __restrict__ Wk,
                                                        const float* __restrict__ Wv,
                                                        const float* __restrict__ Wo)
{
    const int i = blockIdx.x * 256 + threadIdx.x;
    const int NX = MROWS * WPR;
    const int NW = DMODEL * WPR;
    uint32_t h, l;
    if (i < NX) {
        float2 v = ((const float2*)X)[i];
        split2(v.x, v.y, h, l);
        g_xhi[i] = h; g_xlo[i] = l;
    } else {
        int t = i - NX;
        int sel = t >> 19, idx = t & (NW - 1);
        const float* src; uint32_t *dh, *dl;
        if      (sel == 0) { src = Wq; dh = g_wqh; dl = g_wql; }
        else if (sel == 1) { src = Wk; dh = g_wkh; dl = g_wkl; }
        else if (sel == 2) { src = Wv; dh = g_wvh; dl = g_wvl; }
        else               { src = Wo; dh = g_woh; dl = g_wol; }
        float2 v = ((const float2*)src)[idx];
        split2(v.x, v.y, h, l);
        dh[idx] = h; dl[idx] = l;
    }
}

// ---------------- V transpose + fp16 (single plane) pre-pass ----------------
__global__ void __launch_bounds__(256) vtrans_kernel()
{
    __shared__ float vs[64 * 65];
    const int j = blockIdx.x, bh = blockIdx.y;
    const int tid = threadIdx.x;
    const float* src = g_v + (size_t)bh * (SEQ * HDIM) + (size_t)j * 64 * HDIM;
#pragma unroll
    for (int it = 0; it < 16; it++) {
        const int i = tid + it * 256;
        const int kv = i >> 6, hd = i & 63;
        vs[kv * 65 + hd] = src[kv * 64 + hd];
    }
    __syncthreads();
    const size_t obase = ((size_t)bh * 32 + j) * 2048;
#pragma unroll
    for (int it = 0; it < 8; it++) {
        const int i = tid + it * 256;
        const int hd = i >> 5, w = i & 31;
        g_vth[obase + hd * 32 + w] = pack_h2f(vs[(2 * w) * 65 + hd], vs[(2 * w + 1) * 65 + hd]);
    }
}

// ---------------- bf16-split GEMM: 512 thr, 128x256 tile, BK=64, 2-stage ----------------
#define GSTGW 24576
#define GEMM_SMEM (2 * GSTGW * 4)   // 192KB

__device__ __forceinline__ void gemm_body(const uint32_t* __restrict__ Ah,
                                          const uint32_t* __restrict__ Al,
                                          const uint32_t* __restrict__ Bh,
                                          const uint32_t* __restrict__ Bl,
                                          int mode, float oscale,
                                          float* __restrict__ Cf,
                                          uint32_t* __restrict__ OH,
                                          uint32_t* __restrict__ OL,
                                          const float* __restrict__ bias)
{
    extern __shared__ uint32_t sm[];
    const uint32_t smu = smem_u32(sm);
    const int tid = threadIdx.x;
    const int wid = tid >> 5, lane = tid & 31;
    const int gr = lane >> 2, tg = lane & 3;
    const int m0 = blockIdx.y * 128, n0 = blockIdx.x * 256;
    const int wm = (wid >> 2) * 32, wn = (wid & 3) * 64;

    const int la = lane & 15;
    const int ajbit = lane >> 4;
    const int lb = lane & 7;
    const int bjbit = (lane >> 3) & 1;
    const int bplane = lane >> 4;
    const uint32_t aRow = (uint32_t)(wm + la) * 128;
    const uint32_t bRow = 32768u + (uint32_t)bplane * 32768u + (uint32_t)(wn + lb) * 128;
    const int la7 = la & 7;

    float acc[2][8][4];
#pragma unroll
    for (int i = 0; i < 2; i++)
#pragma unroll
        for (int j = 0; j < 8; j++)
#pragma unroll
            for (int c = 0; c < 4; c++) acc[i][j][c] = 0.f;

    auto load_stage = [&](int kt, int stg) {
        const uint32_t sb = smu + stg * GSTGW * 4;
#pragma unroll
        for (int it = 0; it < 12; it++) {
            const int c = tid + it * 512;
            const uint32_t* src;
            uint32_t wordoff;
            if (c < 2048) {
                const int r = (c >> 3) & 127, jj = c & 7;
                wordoff = ((c >> 10) ? 4096u : 0u) + r * 32 + ((jj ^ (r & 7)) << 2);
                src = ((c >> 10) ? Al : Ah) + (size_t)(m0 + r) * WPR + kt * 32 + jj * 4;
            } else {
                const int cb = c - 2048;
                const int r = (cb >> 3) & 255, jj = cb & 7;
                wordoff = ((cb >> 11) ? 16384u : 8192u) + r * 32 + ((jj ^ (r & 7)) << 2);
                src = ((cb >> 11) ? Bl : Bh) + (size_t)(n0 + r) * WPR + kt * 32 + jj * 4;
            }
            cp_async16(sb + wordoff * 4, src);
        }
    };

    load_stage(0, 0); CP_COMMIT();
    load_stage(1, 1); CP_COMMIT();

    for (int kt = 0; kt < 16; kt++) {
        CP_WAIT(1);
        __syncthreads();
        const uint32_t stageB = smu + (kt & 1) * GSTGW * 4;
#pragma unroll
        for (int kc = 0; kc < 4; kc++) {
            const uint32_t aswz = (uint32_t)(((2 * kc + ajbit) ^ la7) << 4);
            const uint32_t bswz = (uint32_t)(((2 * kc + bjbit) ^ lb) << 4);
            uint32_t ah[2][4], al[2][4];
#pragma unroll
            for (int mi = 0; mi < 2; mi++) {
                const uint32_t abase = stageB + aRow + mi * 2048 + aswz;
                ldsm_x4(ah[mi][0], ah[mi][1], ah[mi][2], ah[mi][3], abase);
                ldsm_x4(al[mi][0], al[mi][1], al[mi][2], al[mi][3], abase + 16384);
            }
#pragma unroll
            for (int njb = 0; njb < 2; njb++) {
                uint32_t bf[4][4];
#pragma unroll
                for (int q = 0; q < 4; q++)
                    ldsm_x4(bf[q][0], bf[q][1], bf[q][2], bf[q][3],
                            stageB + bRow + (njb * 4 + q) * 1024 + bswz);
#pragma unroll
                for (int q = 0; q < 4; q++)
#pragma unroll
                    for (int mi = 0; mi < 2; mi++)
                        mma_bf16(acc[mi][njb * 4 + q], ah[mi], &bf[q][0]);
#pragma unroll
                for (int q = 0; q < 4; q++)
#pragma unroll
                    for (int mi = 0; mi < 2; mi++)
                        mma_bf16(acc[mi][njb * 4 + q], ah[mi], &bf[q][2]);
#pragma unroll
                for (int q = 0; q < 4; q++)
#pragma unroll
                    for (int mi = 0; mi < 2; mi++)
                        mma_bf16(acc[mi][njb * 4 + q], al[mi], &bf[q][0]);
            }
        }
        __syncthreads();
        if (kt + 2 < 16) load_stage(kt + 2, kt & 1);
        CP_COMMIT();
    }

#pragma unroll
    for (int mi = 0; mi < 2; mi++) {
        const int r0 = m0 + wm + mi * 16 + gr;
#pragma unroll
        for (int nj = 0; nj < 8; nj++) {
            const int c0 = n0 + wn + nj * 8 + 2 * tg;
            float v0 = acc[mi][nj][0], v1 = acc[mi][nj][1];
            float v2 = acc[mi][nj][2], v3 = acc[mi][nj][3];
            if (mode == 0) {
                v0 *= oscale; v1 *= oscale; v2 *= oscale; v3 *= oscale;
                uint32_t h, l;
                split2(v0, v1, h, l);
                OH[(size_t)r0 * WPR + (c0 >> 1)] = h;
                OL[(size_t)r0 * WPR + (c0 >> 1)] = l;
                split2(v2, v3, h, l);
                OH[(size_t)(r0 + 8) * WPR + (c0 >> 1)] = h;
                OL[(size_t)(r0 + 8) * WPR + (c0 >> 1)] = l;
            } else {
                if (mode == 2) {
                    const float b0 = bias[c0], b1 = bias[c0 + 1];
                    v0 += b0; v1 += b1; v2 += b0; v3 += b1;
                }
                *(float2*)(Cf + (size_t)r0 * DMODEL + c0) = make_float2(v0, v1);
                *(float2*)(Cf + (size_t)(r0 + 8) * DMODEL + c0) = make_float2(v2, v3);
            }
        }
    }
}

__global__ void __launch_bounds__(512) qkv_kernel()
{
    const int z = blockIdx.z;
    if (z == 0)      gemm_body(g_xhi, g_xlo, g_wqh, g_wql, 0, LOG2E, nullptr, g_qh, g_ql, nullptr);
    else if (z == 1) gemm_body(g_xhi, g_xlo, g_wkh, g_wkl, 0, 1.0f, nullptr, g_kh, g_kl, nullptr);
    else             gemm_body(g_xhi, g_xlo, g_wvh, g_wvl, 1, 1.0f, g_v, nullptr, nullptr, nullptr);
}

__global__ void __launch_bounds__(512) out_kernel(const float* __restrict__ bias,
                                                  float* __restrict__ out)
{
    gemm_body(g_ah, g_al, g_woh, g_wol, 2, 1.0f, out, nullptr, nullptr, bias);
}

// ---------------- tensor-core causal flash attention ----------------
// 4-stage pipeline; stage (words): KH[0..2047] | KL[2048..4095] | VT[4096..6143] (24KB)
// QK: bf16 3-term (Q pre-scaled log2e). PV: fp16 P x fp16 V (single plane).
#define ASTGW 6144
#define ATT_SMEM (4 * ASTGW * 4)   // 96KB
#define ONES_H2 0x3C003C00u

__global__ void __launch_bounds__(256, 2) attn_kernel()
{
    extern __shared__ uint32_t sm[];
    const uint32_t smu = smem_u32(sm);
    const int tid = threadIdx.x;
    const int wid = tid >> 5, lane = tid & 31;
    const int gr = lane >> 2, tg = lane & 3;
    const int qi = 15 - blockIdx.x;
    const int bh = blockIdx.y;
    const int qbase = qi * 128;
    const size_t wbase = (size_t)bh * 65536;
    const size_t vtbase = (size_t)bh * 65536;

    const int lb = lane & 7;
    const int bjbit = (lane >> 3) & 1;
    const int bplane = lane >> 4;
    const uint32_t kRow = (uint32_t)bplane * 8192u + (uint32_t)lb * 128;   // KH/KL planes
    const uint32_t vBase = 16384u + (uint32_t)lb * 128;                    // VT single plane

    // ---- stage Q packed (QH words 0..4095, QL 4096..8191; fits in stages 0-1) ----
#pragma unroll
    for (int it = 0; it < 4; it++) {
        const int i = tid + it * 256;
        const int r = i >> 3, j = i & 7;
        const uint32_t dst = (r * 32 + ((j ^ (r & 7)) << 2)) * 4;
        cp_async16(smu + dst, g_qh + wbase + (size_t)(qbase + r) * 32 + j * 4);
        cp_async16(smu + (4096 * 4) + dst, g_ql + wbase + (size_t)(qbase + r) * 32 + j * 4);
    }
    CP_COMMIT(); CP_WAIT(0);
    __syncthreads();

    uint32_t qh[4][4], ql[4][4];
    {
        const int r = wid * 16 + gr;
#pragma unroll
        for (int kc = 0; kc < 4; kc++) {
            const int ch0 = ((2 * kc) ^ (r & 7)) << 2;
            const int ch1 = ((2 * kc + 1) ^ (r & 7)) << 2;
            qh[kc][0] = sm[r * 32 + ch0 + tg];
            qh[kc][1] = sm[(r + 8) * 32 + ch0 + tg];
            qh[kc][2] = sm[r * 32 + ch1 + tg];
            qh[kc][3] = sm[(r + 8) * 32 + ch1 + tg];
            ql[kc][0] = sm[4096 + r * 32 + ch0 + tg];
            ql[kc][1] = sm[4096 + (r + 8) * 32 + ch0 + tg];
            ql[kc][2] = sm[4096 + r * 32 + ch1 + tg];
            ql[kc][3] = sm[4096 + (r + 8) * 32 + ch1 + tg];
        }
    }
    __syncthreads();

    float m0 = -1e30f, m1 = -1e30f;
    float lacc[4] = {0.f, 0.f, 0.f, 0.f};
    float oacc[8][4];
#pragma unroll
    for (int nf = 0; nf < 8; nf++)
#pragma unroll
        for (int c = 0; c < 4; c++) oacc[nf][c] = 0.f;

    const int numj = 2 * qi + 2;

    // KH | KL | VT : 1536 16B-chunks per tile, 6 iters x 256 threads
    auto load_kv = [&](int j, int st) {
        const uint32_t sb = smu + st * ASTGW * 4;
#pragma unroll
        for (int it = 0; it < 6; it++) {
            const int c = tid + it * 256;
            const int part = c >> 9;
            const int r = (c >> 3) & 63;
            const int jj = c & 7;
            const uint32_t dst = sb + (part * 2048 + r * 32 + ((jj ^ (r & 7)) << 2)) * 4;
            const uint32_t* src;
            if      (part == 0) src = g_kh + wbase + (size_t)(j * 64 + r) * 32;
            else if (part == 1) src = g_kl + wbase + (size_t)(j * 64 + r) * 32;
            else                src = g_vth + vtbase + (size_t)j * 2048 + r * 32;
            cp_async16(dst, src + jj * 4);
        }
    };

    load_kv(0, 0); CP_COMMIT();
    if (numj > 1) load_kv(1, 1);
    CP_COMMIT();
    if (numj > 2) load_kv(2, 2);
    CP_COMMIT();

    const uint32_t bones[2] = { ONES_H2, ONES_H2 };

    for (int j = 0; j < numj; j++) {
        CP_WAIT(2);
        __syncthreads();
        if (j + 3 < numj) load_kv(j + 3, (j + 3) & 3);
        CP_COMMIT();

        const uint32_t stageB = smu + (j & 3) * (ASTGW * 4);
        const int kvb = j * 64;

        // ---- S' = (log2e*Q) K^T (bf16 3-term) ----
        float s[8][4];
#pragma unroll
        for (int nf = 0; nf < 8; nf++)
#pragma unroll
            for (int c = 0; c < 4; c++) s[nf][c] = 0.f;
#pragma unroll
        for (int kc = 0; kc < 4; kc++) {
            const uint32_t bswz = (uint32_t)(((2 * kc + bjbit) ^ lb) << 4);
#pragma unroll
            for (int np = 0; np < 4; np++) {
                const int nf0 = 2 * np, nf1 = nf0 + 1;
                uint32_t k0[4], k1[4];
                ldsm_x4(k0[0], k0[1], k0[2], k0[3], stageB + kRow + nf0 * 1024 + bswz);
                ldsm_x4(k1[0], k1[1], k1[2], k1[3], stageB + kRow + nf1 * 1024 + bswz);
                mma_bf16(s[nf0], qh[kc], &k0[0]);
                mma_bf16(s[nf1], qh[kc], &k1[0]);
                mma_bf16(s[nf0], qh[kc], &k0[2]);
                mma_bf16(s[nf1], qh[kc], &k1[2]);
                mma_bf16(s[nf0], ql[kc], &k0[0]);
                mma_bf16(s[nf1], ql[kc], &k1[0]);
            }
        }

        if (j >= 2 * qi) {
            const int row0 = qbase + wid * 16 + gr, row1 = row0 + 8;
#pragma unroll
            for (int nf = 0; nf < 8; nf++) {
                const int col = kvb + nf * 8 + 2 * tg;
                if (col > row0)     s[nf][0] = -1e30f;
                if (col + 1 > row0) s[nf][1] = -1e30f;
                if (col > row1)     s[nf][2] = -1e30f;
                if (col + 1 > row1) s[nf][3] = -1e30f;
            }
        }

        float rm0 = -1e30f, rm1 = -1e30f;
#pragma unroll
        for (int nf = 0; nf < 8; nf++) {
            rm0 = fmaxf(rm0, fmaxf(s[nf][0], s[nf][1]));
            rm1 = fmaxf(rm1, fmaxf(s[nf][2], s[nf][3]));
        }
        rm0 = fmaxf(rm0, __shfl_xor_sync(0xffffffffu, rm0, 1));
        rm0 = fmaxf(rm0, __shfl_xor_sync(0xffffffffu, rm0, 2));
        rm1 = fmaxf(rm1, __shfl_xor_sync(0xffffffffu, rm1, 1));
        rm1 = fmaxf(rm1, __shfl_xor_sync(0xffffffffu, rm1, 2));
        const float mn0 = fmaxf(m0, rm0), mn1 = fmaxf(m1, rm1);
        const float sc0 = exp2f(m0 - mn0), sc1 = exp2f(m1 - mn1);
        m0 = mn0; m1 = mn1;
#pragma unroll
        for (int nf = 0; nf < 8; nf++) {
            oacc[nf][0] *= sc0; oacc[nf][1] *= sc0;
            oacc[nf][2] *= sc1; oacc[nf][3] *= sc1;
        }
        lacc[0] *= sc0; lacc[1] *= sc0; lacc[2] *= sc1; lacc[3] *= sc1;

        // ---- P = exp2(s'-m') fp16; l += P·1; O += P V (single-plane fp16) ----
#pragma unroll
        for (int kc = 0; kc < 4; kc++) {
            const uint32_t vswz = (uint32_t)(((2 * kc + bjbit) ^ lb) << 4);
            uint32_t pa[4];
            pa[0] = exp2_h2(s[2 * kc][0] - mn0,     s[2 * kc][1] - mn0);
            pa[1] = exp2_h2(s[2 * kc][2] - mn1,     s[2 * kc][3] - mn1);
            pa[2] = exp2_h2(s[2 * kc + 1][0] - mn0, s[2 * kc + 1][1] - mn0);
            pa[3] = exp2_h2(s[2 * kc + 1][2] - mn1, s[2 * kc + 1][3] - mn1);
            mma_f16(lacc, pa, bones);
#pragma unroll
            for (int np = 0; np < 4; np++) {
                const int nf0 = 2 * np, nf1 = nf0 + 1;
                uint32_t v0[2], v1[2];
                ldsm_x2(v0[0], v0[1], stageB + vBase + nf0 * 1024 + vswz);
                ldsm_x2(v1[0], v1[1], stageB + vBase + nf1 * 1024 + vswz);
                mma_f16(oacc[nf0], pa, v0);
                mma_f16(oacc[nf1], pa, v1);
            }
        }
    }

    const float inv0 = 1.f / lacc[0], inv1 = 1.f / lacc[2];
    const int row0 = qbase + wid * 16 + gr;
#pragma unroll
    for (int nf = 0; nf < 8; nf++) {
        uint32_t h, l;
        split2(oacc[nf][0] * inv0, oacc[nf][1] * inv0, h, l);
        const int w = nf * 4 + tg;
        g_ah[wbase + (size_t)row0 * 32 + w] = h;
        g_al[wbase + (size_t)row0 * 32 + w] = l;
        split2(oacc[nf][2] * inv1, oacc[nf][3] * inv1, h, l);
        g_ah[wbase + (size_t)(row0 + 8) * 32 + w] = h;
        g_al[wbase + (size_t)(row0 + 8) * 32 + w] = l;
    }
}

// ---------------------------------------------------------------------------
extern "C" void kernel_launch(void* const* d_in, const int* in_sizes, int n_in,
                              void* d_out, int out_size)
{
    const float* X  = (const float*)d_in[0];
    const float* Wq = (const float*)d_in[1];
    const float* Wk = (const float*)d_in[2];
    const float* Wv = (const float*)d_in[3];
    const float* Wo = (const float*)d_in[4];
    const float* bo = (const float*)d_in[5];
    float* out = (float*)d_out;

    cudaFuncSetAttribute(qkv_kernel, cudaFuncAttributeMaxDynamicSharedMemorySize, GEMM_SMEM);
    cudaFuncSetAttribute(out_kernel, cudaFuncAttributeMaxDynamicSharedMemorySize, GEMM_SMEM);
    cudaFuncSetAttribute(attn_kernel, cudaFuncAttributeMaxDynamicSharedMemorySize, ATT_SMEM);

    const int total_words = MROWS * WPR + 4 * DMODEL * WPR;
    split_all_kernel<<<total_words / 256, 256>>>(X, Wq, Wk, Wv, Wo);
    qkv_kernel<<<dim3(DMODEL / 256, MROWS / 128, 3), 512, GEMM_SMEM>>>();
    vtrans_kernel<<<dim3(32, BHCNT), 256>>>();
    attn_kernel<<<dim3(16, BHCNT), 256, ATT_SMEM>>>();
    out_kernel<<<dim3(DMODEL / 256, MROWS / 128), 512, GEMM_SMEM>>>(bo, out);
}

// round 15
// speedup vs baseline: 1.1627x; 1.0928x over previous
#include <cuda_runtime.h>
#include <cuda_bf16.h>
#include <cuda_fp16.h>
#include <cstdint>

#define SEQ    2048
#define DMODEL 1024
#define HDIM   64
#define MROWS  4096
#define BHCNT  32
#define WPR    512   // packed 2-elem words per dmodel row
#define LOG2E  1.4426950408889634f

// ---------------- device scratch (allocation-free rule) ----------------
__device__ uint32_t g_xhi[MROWS*WPR], g_xlo[MROWS*WPR];
__device__ uint32_t g_wqh[DMODEL*WPR], g_wql[DMODEL*WPR];
__device__ uint32_t g_wkh[DMODEL*WPR], g_wkl[DMODEL*WPR];
__device__ uint32_t g_wvh[DMODEL*WPR], g_wvl[DMODEL*WPR];
__device__ uint32_t g_woh[DMODEL*WPR], g_wol[DMODEL*WPR];
__device__ uint32_t g_qh [MROWS*WPR], g_ql [MROWS*WPR];   // fp16 split (log2e-scaled)
__device__ uint32_t g_kh [MROWS*WPR];                     // fp16 single plane
__device__ float    g_v  [MROWS*DMODEL];
__device__ uint32_t g_vth[BHCNT*32*64*32];                // single-plane fp16 V^T
__device__ uint32_t g_ah [MROWS*WPR], g_al [MROWS*WPR];

// ---------------- helpers ----------------
__device__ __forceinline__ uint32_t smem_u32(const void* p) {
    uint32_t a;
    asm("{ .reg .u64 t; cvta.to.shared.u64 t, %1; cvt.u32.u64 %0, t; }" : "=r"(a) : "l"(p));
    return a;
}
__device__ __forceinline__ void cp_async16(uint32_t s, const void* g) {
    asm volatile("cp.async.cg.shared.global [%0], [%1], 16;" ::"r"(s), "l"(g) : "memory");
}
#define CP_COMMIT() asm volatile("cp.async.commit_group;" ::: "memory")
#define CP_WAIT(n)  asm volatile("cp.async.wait_group %0;" ::"n"(n) : "memory")

__device__ __forceinline__ void ldsm_x4(uint32_t& r0, uint32_t& r1, uint32_t& r2, uint32_t& r3,
                                        uint32_t addr) {
    asm volatile("ldmatrix.sync.aligned.m8n8.x4.shared.b16 {%0,%1,%2,%3}, [%4];"
                 : "=r"(r0), "=r"(r1), "=r"(r2), "=r"(r3) : "r"(addr));
}
__device__ __forceinline__ void ldsm_x2(uint32_t& r0, uint32_t& r1, uint32_t addr) {
    asm volatile("ldmatrix.sync.aligned.m8n8.x2.shared.b16 {%0,%1}, [%2];"
                 : "=r"(r0), "=r"(r1) : "r"(addr));
}

// bf16 split (even elem in low half)
__device__ __forceinline__ void split2(float f0, float f1, uint32_t& hw, uint32_t& lw) {
    __nv_bfloat16 h0 = __float2bfloat16(f0), h1 = __float2bfloat16(f1);
    float r0 = f0 - __bfloat162float(h0);
    float r1 = f1 - __bfloat162float(h1);
    __nv_bfloat16 e0 = __float2bfloat16(r0), e1 = __float2bfloat16(r1);
    hw = (uint32_t)__bfloat16_as_ushort(h0) | ((uint32_t)__bfloat16_as_ushort(h1) << 16);
    lw = (uint32_t)__bfloat16_as_ushort(e0) | ((uint32_t)__bfloat16_as_ushort(e1) << 16);
}
// fp16 split (even elem in low half)
__device__ __forceinline__ void split2h(float f0, float f1, uint32_t& hw, uint32_t& lw) {
    __half h0 = __float2half_rn(f0), h1 = __float2half_rn(f1);
    float r0 = f0 - __half2float(h0);
    float r1 = f1 - __half2float(h1);
    __half2 hp = __halves2half2(h0, h1);
    __half2 lp = __halves2half2(__float2half_rn(r0), __float2half_rn(r1));
    hw = *(uint32_t*)&hp;
    lw = *(uint32_t*)&lp;
}
__device__ __forceinline__ uint32_t pack_h2f(float f0, float f1) {
    __half2 h = __floats2half2_rn(f0, f1);
    return *(uint32_t*)&h;
}
__device__ __forceinline__ uint32_t exp2_h2(float a, float b) {
    __half2 h = h2exp2(__floats2half2_rn(a, b));
    return *(uint32_t*)&h;
}
__device__ __forceinline__ void mma_bf16(float* c, const uint32_t* a, const uint32_t* b) {
    asm volatile(
        "mma.sync.aligned.m16n8k16.row.col.f32.bf16.bf16.f32 "
        "{%0,%1,%2,%3}, {%4,%5,%6,%7}, {%8,%9}, {%0,%1,%2,%3};"
        : "+f"(c[0]), "+f"(c[1]), "+f"(c[2]), "+f"(c[3])
        : "r"(a[0]), "r"(a[1]), "r"(a[2]), "r"(a[3]), "r"(b[0]), "r"(b[1]));
}
__device__ __forceinline__ void mma_f16(float* c, const uint32_t* a, const uint32_t* b) {
    asm volatile(
        "mma.sync.aligned.m16n8k16.row.col.f32.f16.f16.f32 "
        "{%0,%1,%2,%3}, {%4,%5,%6,%7}, {%8,%9}, {%0,%1,%2,%3};"
        : "+f"(c[0]), "+f"(c[1]), "+f"(c[2]), "+f"(c[3])
        : "r"(a[0]), "r"(a[1]), "r"(a[2]), "r"(a[3]), "r"(b[0]), "r"(b[1]));
}

// ---------------- pre-split pass ----------------
__global__ void __launch_bounds__(256) split_all_kernel(const float* __restrict__ X,
                                                        const float* __restrict__ Wq,
                                                        const float* __restrict__ Wk,
                                                        const float* __restrict__ Wv,
                                                        const float* __restrict__ Wo)
{
    const int i = blockIdx.x * 256 + threadIdx.x;
    const int NX = MROWS * WPR;
    const int NW = DMODEL * WPR;
    uint32_t h, l;
    if (i < NX) {
        float2 v = ((const float2*)X)[i];
        split2(v.x, v.y, h, l);
        g_xhi[i] = h; g_xlo[i] = l;
    } else {
        int t = i - NX;
        int sel = t >> 19, idx = t & (NW - 1);
        const float* src; uint32_t *dh, *dl;
        if      (sel == 0) { src = Wq; dh = g_wqh; dl = g_wql; }
        else if (sel == 1) { src = Wk; dh = g_wkh; dl = g_wkl; }
        else if (sel == 2) { src = Wv; dh = g_wvh; dl = g_wvl; }
        else               { src = Wo; dh = g_woh; dl = g_wol; }
        float2 v = ((const float2*)src)[idx];
        split2(v.x, v.y, h, l);
        dh[idx] = h; dl[idx] = l;
    }
}

// ---------------- V transpose + fp16 (single plane) pre-pass ----------------
__global__ void __launch_bounds__(256) vtrans_kernel()
{
    __shared__ float vs[64 * 65];
    const int j = blockIdx.x, bh = blockIdx.y;
    const int tid = threadIdx.x;
    const float* src = g_v + (size_t)bh * (SEQ * HDIM) + (size_t)j * 64 * HDIM;
#pragma unroll
    for (int it = 0; it < 16; it++) {
        const int i = tid + it * 256;
        const int kv = i >> 6, hd = i & 63;
        vs[kv * 65 + hd] = src[kv * 64 + hd];
    }
    __syncthreads();
    const size_t obase = ((size_t)bh * 32 + j) * 2048;
#pragma unroll
    for (int it = 0; it < 8; it++) {
        const int i = tid + it * 256;
        const int hd = i >> 5, w = i & 31;
        g_vth[obase + hd * 32 + w] = pack_h2f(vs[(2 * w) * 65 + hd], vs[(2 * w + 1) * 65 + hd]);
    }
}

// ---------------- bf16-split GEMM: 512 thr, 128x256 tile, BK=64, 2-stage ----------------
// mode: 0 = fp16-split out (Q, scaled), 1 = fp32 out, 2 = fp32+bias, 3 = fp16 single (K)
#define GSTGW 24576
#define GEMM_SMEM (2 * GSTGW * 4)   // 192KB

__device__ __forceinline__ void gemm_body(const uint32_t* __restrict__ Ah,
                                          const uint32_t* __restrict__ Al,
                                          const uint32_t* __restrict__ Bh,
                                          const uint32_t* __restrict__ Bl,
                                          int mode, float oscale,
                                          float* __restrict__ Cf,
                                          uint32_t* __restrict__ OH,
                                          uint32_t* __restrict__ OL,
                                          const float* __restrict__ bias)
{
    extern __shared__ uint32_t sm[];
    const uint32_t smu = smem_u32(sm);
    const int tid = threadIdx.x;
    const int wid = tid >> 5, lane = tid & 31;
    const int gr = lane >> 2, tg = lane & 3;
    const int m0 = blockIdx.y * 128, n0 = blockIdx.x * 256;
    const int wm = (wid >> 2) * 32, wn = (wid & 3) * 64;

    const int la = lane & 15;
    const int ajbit = lane >> 4;
    const int lb = lane & 7;
    const int bjbit = (lane >> 3) & 1;
    const int bplane = lane >> 4;
    const uint32_t aRow = (uint32_t)(wm + la) * 128;
    const uint32_t bRow = 32768u + (uint32_t)bplane * 32768u + (uint32_t)(wn + lb) * 128;
    const int la7 = la & 7;

    float acc[2][8][4];
#pragma unroll
    for (int i = 0; i < 2; i++)
#pragma unroll
        for (int j = 0; j < 8; j++)
#pragma unroll
            for (int c = 0; c < 4; c++) acc[i][j][c] = 0.f;

    auto load_stage = [&](int kt, int stg) {
        const uint32_t sb = smu + stg * GSTGW * 4;
#pragma unroll
        for (int it = 0; it < 12; it++) {
            const int c = tid + it * 512;
            const uint32_t* src;
            uint32_t wordoff;
            if (c < 2048) {
                const int r = (c >> 3) & 127, jj = c & 7;
                wordoff = ((c >> 10) ? 4096u : 0u) + r * 32 + ((jj ^ (r & 7)) << 2);
                src = ((c >> 10) ? Al : Ah) + (size_t)(m0 + r) * WPR + kt * 32 + jj * 4;
            } else {
                const int cb = c - 2048;
                const int r = (cb >> 3) & 255, jj = cb & 7;
                wordoff = ((cb >> 11) ? 16384u : 8192u) + r * 32 + ((jj ^ (r & 7)) << 2);
                src = ((cb >> 11) ? Bl : Bh) + (size_t)(n0 + r) * WPR + kt * 32 + jj * 4;
            }
            cp_async16(sb + wordoff * 4, src);
        }
    };

    load_stage(0, 0); CP_COMMIT();
    load_stage(1, 1); CP_COMMIT();

    for (int kt = 0; kt < 16; kt++) {
        CP_WAIT(1);
        __syncthreads();
        const uint32_t stageB = smu + (kt & 1) * GSTGW * 4;
#pragma unroll
        for (int kc = 0; kc < 4; kc++) {
            const uint32_t aswz = (uint32_t)(((2 * kc + ajbit) ^ la7) << 4);
            const uint32_t bswz = (uint32_t)(((2 * kc + bjbit) ^ lb) << 4);
            uint32_t ah[2][4], al[2][4];
#pragma unroll
            for (int mi = 0; mi < 2; mi++) {
                const uint32_t abase = stageB + aRow + mi * 2048 + aswz;
                ldsm_x4(ah[mi][0], ah[mi][1], ah[mi][2], ah[mi][3], abase);
                ldsm_x4(al[mi][0], al[mi][1], al[mi][2], al[mi][3], abase + 16384);
            }
#pragma unroll
            for (int njb = 0; njb < 2; njb++) {
                uint32_t bf[4][4];
#pragma unroll
                for (int q = 0; q < 4; q++)
                    ldsm_x4(bf[q][0], bf[q][1], bf[q][2], bf[q][3],
                            stageB + bRow + (njb * 4 + q) * 1024 + bswz);
#pragma unroll
                for (int q = 0; q < 4; q++)
#pragma unroll
                    for (int mi = 0; mi < 2; mi++)
                        mma_bf16(acc[mi][njb * 4 + q], ah[mi], &bf[q][0]);
#pragma unroll
                for (int q = 0; q < 4; q++)
#pragma unroll
                    for (int mi = 0; mi < 2; mi++)
                        mma_bf16(acc[mi][njb * 4 + q], ah[mi], &bf[q][2]);
#pragma unroll
                for (int q = 0; q < 4; q++)
#pragma unroll
                    for (int mi = 0; mi < 2; mi++)
                        mma_bf16(acc[mi][njb * 4 + q], al[mi], &bf[q][0]);
            }
        }
        __syncthreads();
        if (kt + 2 < 16) load_stage(kt + 2, kt & 1);
        CP_COMMIT();
    }

#pragma unroll
    for (int mi = 0; mi < 2; mi++) {
        const int r0 = m0 + wm + mi * 16 + gr;
#pragma unroll
        for (int nj = 0; nj < 8; nj++) {
            const int c0 = n0 + wn + nj * 8 + 2 * tg;
            float v0 = acc[mi][nj][0], v1 = acc[mi][nj][1];
            float v2 = acc[mi][nj][2], v3 = acc[mi][nj][3];
            if (mode == 0) {
                v0 *= oscale; v1 *= oscale; v2 *= oscale; v3 *= oscale;
                uint32_t h, l;
                split2h(v0, v1, h, l);
                OH[(size_t)r0 * WPR + (c0 >> 1)] = h;
                OL[(size_t)r0 * WPR + (c0 >> 1)] = l;
                split2h(v2, v3, h, l);
                OH[(size_t)(r0 + 8) * WPR + (c0 >> 1)] = h;
                OL[(size_t)(r0 + 8) * WPR + (c0 >> 1)] = l;
            } else if (mode == 3) {
                OH[(size_t)r0 * WPR + (c0 >> 1)] = pack_h2f(v0, v1);
                OH[(size_t)(r0 + 8) * WPR + (c0 >> 1)] = pack_h2f(v2, v3);
            } else {
                if (mode == 2) {
                    const float b0 = bias[c0], b1 = bias[c0 + 1];
                    v0 += b0; v1 += b1; v2 += b0; v3 += b1;
                }
                *(float2*)(Cf + (size_t)r0 * DMODEL + c0) = make_float2(v0, v1);
                *(float2*)(Cf + (size_t)(r0 + 8) * DMODEL + c0) = make_float2(v2, v3);
            }
        }
    }
}

__global__ void __launch_bounds__(512) qkv_kernel()
{
    const int z = blockIdx.z;
    if (z == 0)      gemm_body(g_xhi, g_xlo, g_wqh, g_wql, 0, LOG2E, nullptr, g_qh, g_ql, nullptr);
    else if (z == 1) gemm_body(g_xhi, g_xlo, g_wkh, g_wkl, 3, 1.0f, nullptr, g_kh, nullptr, nullptr);
    else             gemm_body(g_xhi, g_xlo, g_wvh, g_wvl, 1, 1.0f, g_v, nullptr, nullptr, nullptr);
}

__global__ void __launch_bounds__(512) out_kernel(const float* __restrict__ bias,
                                                  float* __restrict__ out)
{
    gemm_body(g_ah, g_al, g_woh, g_wol, 2, 1.0f, out, nullptr, nullptr, bias);
}

// ---------------- tensor-core causal flash attention ----------------
// 4-stage pipeline; stage (words): K[0..2047] | VT[2048..4095] (16KB)
// QK: fp16 2-term (Q=qh+ql fp16 split, K fp16 single). PV: fp16 P x fp16 V.
#define ASTGW 4096
#define ATT_SMEM (4 * ASTGW * 4)   // 64KB
#define ONES_H2 0x3C003C00u

__global__ void __launch_bounds__(256, 2) attn_kernel()
{
    extern __shared__ uint32_t sm[];
    const uint32_t smu = smem_u32(sm);
    const int tid = threadIdx.x;
    const int wid = tid >> 5, lane = tid & 31;
    const int gr = lane >> 2, tg = lane & 3;
    const int qi = 15 - blockIdx.x;
    const int bh = blockIdx.y;
    const int qbase = qi * 128;
    const size_t wbase = (size_t)bh * 65536;
    const size_t vtbase = (size_t)bh * 65536;

    const int lb = lane & 7;
    const int bjbit = (lane >> 3) & 1;
    const uint32_t kBase = (uint32_t)lb * 128;            // K plane (byte off in stage)
    const uint32_t vBase = 8192u + (uint32_t)lb * 128;    // VT plane

    // ---- stage Q packed fp16 (QH words 0..4095, QL 4096..8191 = stages 0-1) ----
#pragma unroll
    for (int it = 0; it < 4; it++) {
        const int i = tid + it * 256;
        const int r = i >> 3, j = i & 7;
        const uint32_t dst = (r * 32 + ((j ^ (r & 7)) << 2)) * 4;
        cp_async16(smu + dst, g_qh + wbase + (size_t)(qbase + r) * 32 + j * 4);
        cp_async16(smu + (4096 * 4) + dst, g_ql + wbase + (size_t)(qbase + r) * 32 + j * 4);
    }
    CP_COMMIT(); CP_WAIT(0);
    __syncthreads();

    uint32_t qh[4][4], ql[4][4];
    {
        const int r = wid * 16 + gr;
#pragma unroll
        for (int kc = 0; kc < 4; kc++) {
            const int ch0 = ((2 * kc) ^ (r & 7)) << 2;
            const int ch1 = ((2 * kc + 1) ^ (r & 7)) << 2;
            qh[kc][0] = sm[r * 32 + ch0 + tg];
            qh[kc][1] = sm[(r + 8) * 32 + ch0 + tg];
            qh[kc][2] = sm[r * 32 + ch1 + tg];
            qh[kc][3] = sm[(r + 8) * 32 + ch1 + tg];
            ql[kc][0] = sm[4096 + r * 32 + ch0 + tg];
            ql[kc][1] = sm[4096 + (r + 8) * 32 + ch0 + tg];
            ql[kc][2] = sm[4096 + r * 32 + ch1 + tg];
            ql[kc][3] = sm[4096 + (r + 8) * 32 + ch1 + tg];
        }
    }
    __syncthreads();

    float m0 = -1e30f, m1 = -1e30f;
    float lacc[4] = {0.f, 0.f, 0.f, 0.f};
    float oacc[8][4];
#pragma unroll
    for (int nf = 0; nf < 8; nf++)
#pragma unroll
        for (int c = 0; c < 4; c++) oacc[nf][c] = 0.f;

    const int numj = 2 * qi + 2;

    // K | VT : 1024 16B-chunks per tile, 4 iters x 256 threads
    auto load_kv = [&](int j, int st) {
        const uint32_t sb = smu + st * ASTGW * 4;
#pragma unroll
        for (int it = 0; it < 4; it++) {
            const int c = tid + it * 256;
            const int part = c >> 9;
            const int r = (c >> 3) & 63;
            const int jj = c & 7;
            const uint32_t dst = sb + (part * 2048 + r * 32 + ((jj ^ (r & 7)) << 2)) * 4;
            const uint32_t* src;
            if (part == 0) src = g_kh + wbase + (size_t)(j * 64 + r) * 32;
            else           src = g_vth + vtbase + (size_t)j * 2048 + r * 32;
            cp_async16(dst, src + jj * 4);
        }
    };

    load_kv(0, 0); CP_COMMIT();
    if (numj > 1) load_kv(1, 1);
    CP_COMMIT();
    if (numj > 2) load_kv(2, 2);
    CP_COMMIT();

    const uint32_t bones[2] = { ONES_H2, ONES_H2 };

    for (int j = 0; j < numj; j++) {
        CP_WAIT(2);
        __syncthreads();
        if (j + 3 < numj) load_kv(j + 3, (j + 3) & 3);
        CP_COMMIT();

        const uint32_t stageB = smu + (j & 3) * (ASTGW * 4);
        const int kvb = j * 64;

        // ---- S' = (log2e*Q) K^T : fp16 2-term ----
        float s[8][4];
#pragma unroll
        for (int nf = 0; nf < 8; nf++)
#pragma unroll
            for (int c = 0; c < 4; c++) s[nf][c] = 0.f;
#pragma unroll
        for (int kc = 0; kc < 4; kc++) {
            const uint32_t kswz = (uint32_t)(((2 * kc + bjbit) ^ lb) << 4);
#pragma unroll
            for (int np = 0; np < 4; np++) {
                const int nf0 = 2 * np, nf1 = nf0 + 1;
                uint32_t k0[2], k1[2];
                ldsm_x2(k0[0], k0[1], stageB + kBase + nf0 * 1024 + kswz);
                ldsm_x2(k1[0], k1[1], stageB + kBase + nf1 * 1024 + kswz);
                mma_f16(s[nf0], qh[kc], k0);
                mma_f16(s[nf1], qh[kc], k1);
                mma_f16(s[nf0], ql[kc], k0);
                mma_f16(s[nf1], ql[kc], k1);
            }
        }

        if (j >= 2 * qi) {
            const int row0 = qbase + wid * 16 + gr, row1 = row0 + 8;
#pragma unroll
            for (int nf = 0; nf < 8; nf++) {
                const int col = kvb + nf * 8 + 2 * tg;
                if (col > row0)     s[nf][0] = -1e30f;
                if (col + 1 > row0) s[nf][1] = -1e30f;
                if (col > row1)     s[nf][2] = -1e30f;
                if (col + 1 > row1) s[nf][3] = -1e30f;
            }
        }

        float rm0 = -1e30f, rm1 = -1e30f;
#pragma unroll
        for (int nf = 0; nf < 8; nf++) {
            rm0 = fmaxf(rm0, fmaxf(s[nf][0], s[nf][1]));
            rm1 = fmaxf(rm1, fmaxf(s[nf][2], s[nf][3]));
        }
        rm0 = fmaxf(rm0, __shfl_xor_sync(0xffffffffu, rm0, 1));
        rm0 = fmaxf(rm0, __shfl_xor_sync(0xffffffffu, rm0, 2));
        rm1 = fmaxf(rm1, __shfl_xor_sync(0xffffffffu, rm1, 1));
        rm1 = fmaxf(rm1, __shfl_xor_sync(0xffffffffu, rm1, 2));
        const float mn0 = fmaxf(m0, rm0), mn1 = fmaxf(m1, rm1);
        const float sc0 = exp2f(m0 - mn0), sc1 = exp2f(m1 - mn1);
        m0 = mn0; m1 = mn1;
#pragma unroll
        for (int nf = 0; nf < 8; nf++) {
            oacc[nf][0] *= sc0; oacc[nf][1] *= sc0;
            oacc[nf][2] *= sc1; oacc[nf][3] *= sc1;
        }
        lacc[0] *= sc0; lacc[1] *= sc0; lacc[2] *= sc1; lacc[3] *= sc1;

        // ---- P = exp2(s'-m') fp16; l += P·1; O += P V ----
#pragma unroll
        for (int kc = 0; kc < 4; kc++) {
            const uint32_t vswz = (uint32_t)(((2 * kc + bjbit) ^ lb) << 4);
            uint32_t pa[4];
            pa[0] = exp2_h2(s[2 * kc][0] - mn0,     s[2 * kc][1] - mn0);
            pa[1] = exp2_h2(s[2 * kc][2] - mn1,     s[2 * kc][3] - mn1);
            pa[2] = exp2_h2(s[2 * kc + 1][0] - mn0, s[2 * kc + 1][1] - mn0);
            pa[3] = exp2_h2(s[2 * kc + 1][2] - mn1, s[2 * kc + 1][3] - mn1);
            mma_f16(lacc, pa, bones);
#pragma unroll
            for (int np = 0; np < 4; np++) {
                const int nf0 = 2 * np, nf1 = nf0 + 1;
                uint32_t v0[2], v1[2];
                ldsm_x2(v0[0], v0[1], stageB + vBase + nf0 * 1024 + vswz);
                ldsm_x2(v1[0], v1[1], stageB + vBase + nf1 * 1024 + vswz);
                mma_f16(oacc[nf0], pa, v0);
                mma_f16(oacc[nf1], pa, v1);
            }
        }
    }

    const float inv0 = 1.f / lacc[0], inv1 = 1.f / lacc[2];
    const int row0 = qbase + wid * 16 + gr;
#pragma unroll
    for (int nf = 0; nf < 8; nf++) {
        uint32_t h, l;
        split2(oacc[nf][0] * inv0, oacc[nf][1] * inv0, h, l);
        const int w = nf * 4 + tg;
        g_ah[wbase + (size_t)row0 * 32 + w] = h;
        g_al[wbase + (size_t)row0 * 32 + w] = l;
        split2(oacc[nf][2] * inv1, oacc[nf][3] * inv1, h, l);
        g_ah[wbase + (size_t)(row0 + 8) * 32 + w] = h;
        g_al[wbase + (size_t)(row0 + 8) * 32 + w] = l;
    }
}

// ---------------------------------------------------------------------------
extern "C" void kernel_launch(void* const* d_in, const int* in_sizes, int n_in,
                              void* d_out, int out_size)
{
    const float* X  = (const float*)d_in[0];
    const float* Wq = (const float*)d_in[1];
    const float* Wk = (const float*)d_in[2];
    const float* Wv = (const float*)d_in[3];
    const float* Wo = (const float*)d_in[4];
    const float* bo = (const float*)d_in[5];
    float* out = (float*)d_out;

    cudaFuncSetAttribute(qkv_kernel, cudaFuncAttributeMaxDynamicSharedMemorySize, GEMM_SMEM);
    cudaFuncSetAttribute(out_kernel, cudaFuncAttributeMaxDynamicSharedMemorySize, GEMM_SMEM);
    cudaFuncSetAttribute(attn_kernel, cudaFuncAttributeMaxDynamicSharedMemorySize, ATT_SMEM);

    const int total_words = MROWS * WPR + 4 * DMODEL * WPR;
    split_all_kernel<<<total_words / 256, 256>>>(X, Wq, Wk, Wv, Wo);
    qkv_kernel<<<dim3(DMODEL / 256, MROWS / 128, 3), 512, GEMM_SMEM>>>();
    vtrans_kernel<<<dim3(32, BHCNT), 256>>>();
    attn_kernel<<<dim3(16, BHCNT), 256, ATT_SMEM>>>();
    out_kernel<<<dim3(DMODEL / 256, MROWS / 128), 512, GEMM_SMEM>>>(bo, out);
}

// round 16
// speedup vs baseline: 1.1641x; 1.0012x over previous
#include <cuda_runtime.h>
#include <cuda_bf16.h>
#include <cuda_fp16.h>
#include <cstdint>

#define SEQ    2048
#define DMODEL 1024
#define HDIM   64
#define MROWS  4096
#define BHCNT  32
#define WPR    512   // packed 2-elem words per dmodel row
#define LOG2E  1.4426950408889634f

// ---------------- device scratch (allocation-free rule) ----------------
__device__ uint32_t g_xhi[MROWS*WPR], g_xlo[MROWS*WPR];
__device__ uint32_t g_wqh[DMODEL*WPR], g_wql[DMODEL*WPR];
__device__ uint32_t g_wkh[DMODEL*WPR], g_wkl[DMODEL*WPR];
__device__ uint32_t g_wvh[DMODEL*WPR], g_wvl[DMODEL*WPR];
__device__ uint32_t g_woh[DMODEL*WPR], g_wol[DMODEL*WPR];
__device__ uint32_t g_qh [MROWS*WPR], g_ql [MROWS*WPR];   // fp16 split (log2e-scaled)
__device__ uint32_t g_kh [MROWS*WPR];                     // fp16 single plane
__device__ float    g_v  [MROWS*DMODEL];
__device__ uint32_t g_vth[BHCNT*32*64*32];                // single-plane fp16 V^T
__device__ uint32_t g_ah [MROWS*WPR], g_al [MROWS*WPR];

// ---------------- helpers ----------------
__device__ __forceinline__ uint32_t smem_u32(const void* p) {
    uint32_t a;
    asm("{ .reg .u64 t; cvta.to.shared.u64 t, %1; cvt.u32.u64 %0, t; }" : "=r"(a) : "l"(p));
    return a;
}
__device__ __forceinline__ void cp_async16(uint32_t s, const void* g) {
    asm volatile("cp.async.cg.shared.global [%0], [%1], 16;" ::"r"(s), "l"(g) : "memory");
}
#define CP_COMMIT() asm volatile("cp.async.commit_group;" ::: "memory")
#define CP_WAIT(n)  asm volatile("cp.async.wait_group %0;" ::"n"(n) : "memory")

__device__ __forceinline__ void ldsm_x4(uint32_t& r0, uint32_t& r1, uint32_t& r2, uint32_t& r3,
                                        uint32_t addr) {
    asm volatile("ldmatrix.sync.aligned.m8n8.x4.shared.b16 {%0,%1,%2,%3}, [%4];"
                 : "=r"(r0), "=r"(r1), "=r"(r2), "=r"(r3) : "r"(addr));
}
__device__ __forceinline__ void ldsm_x2(uint32_t& r0, uint32_t& r1, uint32_t addr) {
    asm volatile("ldmatrix.sync.aligned.m8n8.x2.shared.b16 {%0,%1}, [%2];"
                 : "=r"(r0), "=r"(r1) : "r"(addr));
}

// bf16 split (even elem in low half)
__device__ __forceinline__ void split2(float f0, float f1, uint32_t& hw, uint32_t& lw) {
    __nv_bfloat16 h0 = __float2bfloat16(f0), h1 = __float2bfloat16(f1);
    float r0 = f0 - __bfloat162float(h0);
    float r1 = f1 - __bfloat162float(h1);
    __nv_bfloat16 e0 = __float2bfloat16(r0), e1 = __float2bfloat16(r1);
    hw = (uint32_t)__bfloat16_as_ushort(h0) | ((uint32_t)__bfloat16_as_ushort(h1) << 16);
    lw = (uint32_t)__bfloat16_as_ushort(e0) | ((uint32_t)__bfloat16_as_ushort(e1) << 16);
}
// fp16 split (even elem in low half)
__device__ __forceinline__ void split2h(float f0, float f1, uint32_t& hw, uint32_t& lw) {
    __half h0 = __float2half_rn(f0), h1 = __float2half_rn(f1);
    float r0 = f0 - __half2float(h0);
    float r1 = f1 - __half2float(h1);
    __half2 hp = __halves2half2(h0, h1);
    __half2 lp = __halves2half2(__float2half_rn(r0), __float2half_rn(r1));
    hw = *(uint32_t*)&hp;
    lw = *(uint32_t*)&lp;
}
__device__ __forceinline__ uint32_t pack_h2f(float f0, float f1) {
    __half2 h = __floats2half2_rn(f0, f1);
    return *(uint32_t*)&h;
}
__device__ __forceinline__ uint32_t exp2_h2(float a, float b) {
    __half2 h = h2exp2(__floats2half2_rn(a, b));
    return *(uint32_t*)&h;
}
__device__ __forceinline__ void mma_bf16(float* c, const uint32_t* a, const uint32_t* b) {
    asm volatile(
        "mma.sync.aligned.m16n8k16.row.col.f32.bf16.bf16.f32 "
        "{%0,%1,%2,%3}, {%4,%5,%6,%7}, {%8,%9}, {%0,%1,%2,%3};"
        : "+f"(c[0]), "+f"(c[1]), "+f"(c[2]), "+f"(c[3])
        : "r"(a[0]), "r"(a[1]), "r"(a[2]), "r"(a[3]), "r"(b[0]), "r"(b[1]));
}
__device__ __forceinline__ void mma_f16(float* c, const uint32_t* a, const uint32_t* b) {
    asm volatile(
        "mma.sync.aligned.m16n8k16.row.col.f32.f16.f16.f32 "
        "{%0,%1,%2,%3}, {%4,%5,%6,%7}, {%8,%9}, {%0,%1,%2,%3};"
        : "+f"(c[0]), "+f"(c[1]), "+f"(c[2]), "+f"(c[3])
        : "r"(a[0]), "r"(a[1]), "r"(a[2]), "r"(a[3]), "r"(b[0]), "r"(b[1]));
}

// ---------------- pre-split pass ----------------
__global__ void __launch_bounds__(256) split_all_kernel(const float* __restrict__ X,
                                                        const float* __restrict__ Wq,
                                                        const float* __restrict__ Wk,
                                                        const float* __restrict__ Wv,
                                                        const float* __restrict__ Wo)
{
    const int i = blockIdx.x * 256 + threadIdx.x;
    const int NX = MROWS * WPR;
    const int NW = DMODEL * WPR;
    uint32_t h, l;
    if (i < NX) {
        float2 v = ((const float2*)X)[i];
        split2(v.x, v.y, h, l);
        g_xhi[i] = h; g_xlo[i] = l;
    } else {
        int t = i - NX;
        int sel = t >> 19, idx = t & (NW - 1);
        const float* src; uint32_t *dh, *dl;
        if      (sel == 0) { src = Wq; dh = g_wqh; dl = g_wql; }
        else if (sel == 1) { src = Wk; dh = g_wkh; dl = g_wkl; }
        else if (sel == 2) { src = Wv; dh = g_wvh; dl = g_wvl; }
        else               { src = Wo; dh = g_woh; dl = g_wol; }
        float2 v = ((const float2*)src)[idx];
        split2(v.x, v.y, h, l);
        dh[idx] = h; dl[idx] = l;
    }
}

// ---------------- V transpose + fp16 (single plane) pre-pass ----------------
__global__ void __launch_bounds__(256) vtrans_kernel()
{
    __shared__ float vs[64 * 65];
    const int j = blockIdx.x, bh = blockIdx.y;
    const int tid = threadIdx.x;
    const float* src = g_v + (size_t)bh * (SEQ * HDIM) + (size_t)j * 64 * HDIM;
#pragma unroll
    for (int it = 0; it < 16; it++) {
        const int i = tid + it * 256;
        const int kv = i >> 6, hd = i & 63;
        vs[kv * 65 + hd] = src[kv * 64 + hd];
    }
    __syncthreads();
    const size_t obase = ((size_t)bh * 32 + j) * 2048;
#pragma unroll
    for (int it = 0; it < 8; it++) {
        const int i = tid + it * 256;
        const int hd = i >> 5, w = i & 31;
        g_vth[obase + hd * 32 + w] = pack_h2f(vs[(2 * w) * 65 + hd], vs[(2 * w + 1) * 65 + hd]);
    }
}

// ---------------- bf16-split GEMM: 512 thr, 128x256 tile, BK=64, 2-stage ----------------
// mode: 0 = fp16-split out (Q, scaled), 1 = fp32 out, 2 = fp32+bias, 3 = fp16 single (K)
#define GSTGW 24576
#define GEMM_SMEM (2 * GSTGW * 4)   // 192KB

__device__ __forceinline__ void gemm_body(const uint32_t* __restrict__ Ah,
                                          const uint32_t* __restrict__ Al,
                                          const uint32_t* __restrict__ Bh,
                                          const uint32_t* __restrict__ Bl,
                                          int mode, float oscale,
                                          float* __restrict__ Cf,
                                          uint32_t* __restrict__ OH,
                                          uint32_t* __restrict__ OL,
                                          const float* __restrict__ bias)
{
    extern __shared__ uint32_t sm[];
    const uint32_t smu = smem_u32(sm);
    const int tid = threadIdx.x;
    const int wid = tid >> 5, lane = tid & 31;
    const int gr = lane >> 2, tg = lane & 3;
    const int m0 = blockIdx.y * 128, n0 = blockIdx.x * 256;
    const int wm = (wid >> 2) * 32, wn = (wid & 3) * 64;

    const int la = lane & 15;
    const int ajbit = lane >> 4;
    const int lb = lane & 7;
    const int bjbit = (lane >> 3) & 1;
    const int bplane = lane >> 4;
    const uint32_t aRow = (uint32_t)(wm + la) * 128;
    const uint32_t bRow = 32768u + (uint32_t)bplane * 32768u + (uint32_t)(wn + lb) * 128;
    const int la7 = la & 7;

    float acc[2][8][4];
#pragma unroll
    for (int i = 0; i < 2; i++)
#pragma unroll
        for (int j = 0; j < 8; j++)
#pragma unroll
            for (int c = 0; c < 4; c++) acc[i][j][c] = 0.f;

    auto load_stage = [&](int kt, int stg) {
        const uint32_t sb = smu + stg * GSTGW * 4;
#pragma unroll
        for (int it = 0; it < 12; it++) {
            const int c = tid + it * 512;
            const uint32_t* src;
            uint32_t wordoff;
            if (c < 2048) {
                const int r = (c >> 3) & 127, jj = c & 7;
                wordoff = ((c >> 10) ? 4096u : 0u) + r * 32 + ((jj ^ (r & 7)) << 2);
                src = ((c >> 10) ? Al : Ah) + (size_t)(m0 + r) * WPR + kt * 32 + jj * 4;
            } else {
                const int cb = c - 2048;
                const int r = (cb >> 3) & 255, jj = cb & 7;
                wordoff = ((cb >> 11) ? 16384u : 8192u) + r * 32 + ((jj ^ (r & 7)) << 2);
                src = ((cb >> 11) ? Bl : Bh) + (size_t)(n0 + r) * WPR + kt * 32 + jj * 4;
            }
            cp_async16(sb + wordoff * 4, src);
        }
    };

    load_stage(0, 0); CP_COMMIT();
    load_stage(1, 1); CP_COMMIT();

    for (int kt = 0; kt < 16; kt++) {
        CP_WAIT(1);
        __syncthreads();
        const uint32_t stageB = smu + (kt & 1) * GSTGW * 4;
#pragma unroll
        for (int kc = 0; kc < 4; kc++) {
            const uint32_t aswz = (uint32_t)(((2 * kc + ajbit) ^ la7) << 4);
            const uint32_t bswz = (uint32_t)(((2 * kc + bjbit) ^ lb) << 4);
            uint32_t ah[2][4], al[2][4];
#pragma unroll
            for (int mi = 0; mi < 2; mi++) {
                const uint32_t abase = stageB + aRow + mi * 2048 + aswz;
                ldsm_x4(ah[mi][0], ah[mi][1], ah[mi][2], ah[mi][3], abase);
                ldsm_x4(al[mi][0], al[mi][1], al[mi][2], al[mi][3], abase + 16384);
            }
#pragma unroll
            for (int njb = 0; njb < 2; njb++) {
                uint32_t bf[4][4];
#pragma unroll
                for (int q = 0; q < 4; q++)
                    ldsm_x4(bf[q][0], bf[q][1], bf[q][2], bf[q][3],
                            stageB + bRow + (njb * 4 + q) * 1024 + bswz);
#pragma unroll
                for (int q = 0; q < 4; q++)
#pragma unroll
                    for (int mi = 0; mi < 2; mi++)
                        mma_bf16(acc[mi][njb * 4 + q], ah[mi], &bf[q][0]);
#pragma unroll
                for (int q = 0; q < 4; q++)
#pragma unroll
                    for (int mi = 0; mi < 2; mi++)
                        mma_bf16(acc[mi][njb * 4 + q], ah[mi], &bf[q][2]);
#pragma unroll
                for (int q = 0; q < 4; q++)
#pragma unroll
                    for (int mi = 0; mi < 2; mi++)
                        mma_bf16(acc[mi][njb * 4 + q], al[mi], &bf[q][0]);
            }
        }
        __syncthreads();
        if (kt + 2 < 16) load_stage(kt + 2, kt & 1);
        CP_COMMIT();
    }

#pragma unroll
    for (int mi = 0; mi < 2; mi++) {
        const int r0 = m0 + wm + mi * 16 + gr;
#pragma unroll
        for (int nj = 0; nj < 8; nj++) {
            const int c0 = n0 + wn + nj * 8 + 2 * tg;
            float v0 = acc[mi][nj][0], v1 = acc[mi][nj][1];
            float v2 = acc[mi][nj][2], v3 = acc[mi][nj][3];
            if (mode == 0) {
                v0 *= oscale; v1 *= oscale; v2 *= oscale; v3 *= oscale;
                uint32_t h, l;
                split2h(v0, v1, h, l);
                OH[(size_t)r0 * WPR + (c0 >> 1)] = h;
                OL[(size_t)r0 * WPR + (c0 >> 1)] = l;
                split2h(v2, v3, h, l);
                OH[(size_t)(r0 + 8) * WPR + (c0 >> 1)] = h;
                OL[(size_t)(r0 + 8) * WPR + (c0 >> 1)] = l;
            } else if (mode == 3) {
                OH[(size_t)r0 * WPR + (c0 >> 1)] = pack_h2f(v0, v1);
                OH[(size_t)(r0 + 8) * WPR + (c0 >> 1)] = pack_h2f(v2, v3);
            } else {
                if (mode == 2) {
                    const float b0 = bias[c0], b1 = bias[c0 + 1];
                    v0 += b0; v1 += b1; v2 += b0; v3 += b1;
                }
                *(float2*)(Cf + (size_t)r0 * DMODEL + c0) = make_float2(v0, v1);
                *(float2*)(Cf + (size_t)(r0 + 8) * DMODEL + c0) = make_float2(v2, v3);
            }
        }
    }
}

__global__ void __launch_bounds__(512) qkv_kernel()
{
    const int z = blockIdx.z;
    if (z == 0)      gemm_body(g_xhi, g_xlo, g_wqh, g_wql, 0, LOG2E, nullptr, g_qh, g_ql, nullptr);
    else if (z == 1) gemm_body(g_xhi, g_xlo, g_wkh, g_wkl, 3, 1.0f, nullptr, g_kh, nullptr, nullptr);
    else             gemm_body(g_xhi, g_xlo, g_wvh, g_wvl, 1, 1.0f, g_v, nullptr, nullptr, nullptr);
}

__global__ void __launch_bounds__(512) out_kernel(const float* __restrict__ bias,
                                                  float* __restrict__ out)
{
    gemm_body(g_ah, g_al, g_woh, g_wol, 2, 1.0f, out, nullptr, nullptr, bias);
}

// ---------------- tensor-core causal flash attention ----------------
// 6-stage pipeline; stage (words): K[0..2047] | VT[2048..4095] (16KB).
// Pair-wise loop: ONE CP_WAIT + ONE barrier per TWO kv-tiles (numj always even).
// QK: fp16 2-term (Q=qh+ql fp16 split, K fp16 single). PV: fp16 P x fp16 V.
#define ASTGW 4096
#define ATT_SMEM (6 * ASTGW * 4)   // 96KB
#define ONES_H2 0x3C003C00u

__global__ void __launch_bounds__(256, 2) attn_kernel()
{
    extern __shared__ uint32_t sm[];
    const uint32_t smu = smem_u32(sm);
    const int tid = threadIdx.x;
    const int wid = tid >> 5, lane = tid & 31;
    const int gr = lane >> 2, tg = lane & 3;
    const int qi = 15 - blockIdx.x;
    const int bh = blockIdx.y;
    const int qbase = qi * 128;
    const size_t wbase = (size_t)bh * 65536;
    const size_t vtbase = (size_t)bh * 65536;

    const int lb = lane & 7;
    const int bjbit = (lane >> 3) & 1;
    const uint32_t kBase = (uint32_t)lb * 128;            // K plane (byte off in stage)
    const uint32_t vBase = 8192u + (uint32_t)lb * 128;    // VT plane

    // ---- stage Q packed fp16 (QH words 0..4095, QL 4096..8191 = stages 0-1) ----
#pragma unroll
    for (int it = 0; it < 4; it++) {
        const int i = tid + it * 256;
        const int r = i >> 3, j = i & 7;
        const uint32_t dst = (r * 32 + ((j ^ (r & 7)) << 2)) * 4;
        cp_async16(smu + dst, g_qh + wbase + (size_t)(qbase + r) * 32 + j * 4);
        cp_async16(smu + (4096 * 4) + dst, g_ql + wbase + (size_t)(qbase + r) * 32 + j * 4);
    }
    CP_COMMIT(); CP_WAIT(0);
    __syncthreads();

    uint32_t qh[4][4], ql[4][4];
    {
        const int r = wid * 16 + gr;
#pragma unroll
        for (int kc = 0; kc < 4; kc++) {
            const int ch0 = ((2 * kc) ^ (r & 7)) << 2;
            const int ch1 = ((2 * kc + 1) ^ (r & 7)) << 2;
            qh[kc][0] = sm[r * 32 + ch0 + tg];
            qh[kc][1] = sm[(r + 8) * 32 + ch0 + tg];
            qh[kc][2] = sm[r * 32 + ch1 + tg];
            qh[kc][3] = sm[(r + 8) * 32 + ch1 + tg];
            ql[kc][0] = sm[4096 + r * 32 + ch0 + tg];
            ql[kc][1] = sm[4096 + (r + 8) * 32 + ch0 + tg];
            ql[kc][2] = sm[4096 + r * 32 + ch1 + tg];
            ql[kc][3] = sm[4096 + (r + 8) * 32 + ch1 + tg];
        }
    }
    __syncthreads();

    float m0 = -1e30f, m1 = -1e30f;
    float lacc[4] = {0.f, 0.f, 0.f, 0.f};
    float oacc[8][4];
#pragma unroll
    for (int nf = 0; nf < 8; nf++)
#pragma unroll
        for (int c = 0; c < 4; c++) oacc[nf][c] = 0.f;

    const int numj = 2 * qi + 2;   // always even

    // K | VT : 1024 16B-chunks per tile, 4 iters x 256 threads
    auto load_kv = [&](int j, int st) {
        const uint32_t sb = smu + st * ASTGW * 4;
#pragma unroll
        for (int it = 0; it < 4; it++) {
            const int c = tid + it * 256;
            const int part = c >> 9;
            const int r = (c >> 3) & 63;
            const int jj = c & 7;
            const uint32_t dst = sb + (part * 2048 + r * 32 + ((jj ^ (r & 7)) << 2)) * 4;
            const uint32_t* src;
            if (part == 0) src = g_kh + wbase + (size_t)(j * 64 + r) * 32;
            else           src = g_vth + vtbase + (size_t)j * 2048 + r * 32;
            cp_async16(dst, src + jj * 4);
        }
    };

    // Prologue: prefetch tiles 0..3 (one commit per tile, unconditional)
    load_kv(0, 0);                 CP_COMMIT();
    if (numj > 1) load_kv(1, 1);   CP_COMMIT();
    if (numj > 2) load_kv(2, 2);   CP_COMMIT();
    if (numj > 3) load_kv(3, 3);   CP_COMMIT();

    const uint32_t bones[2] = { ONES_H2, ONES_H2 };

    int stC = 0;      // stage of tile j
    int stL = 4;      // stage for tile j+4
    for (int j = 0; j < numj; j += 2) {
        CP_WAIT(2);               // tiles j, j+1 resident
        __syncthreads();          // prior pair's reads done -> stages stL, stL+1 free
        {
            if (j + 4 < numj) load_kv(j + 4, stL);
            CP_COMMIT();
            int stL2 = stL + 1; if (stL2 == 6) stL2 = 0;
            if (j + 5 < numj) load_kv(j + 5, stL2);
            CP_COMMIT();
            stL = stL2 + 1; if (stL == 6) stL = 0;
        }

        for (int h = 0; h < 2; h++) {
            const int jt = j + h;
            int stg = stC + h; if (stg >= 6) stg -= 6;
            const uint32_t stageB = smu + (uint32_t)stg * (ASTGW * 4);
            const int kvb = jt * 64;

            // ---- S' = (log2e*Q) K^T : fp16 2-term ----
            float s[8][4];
#pragma unroll
            for (int nf = 0; nf < 8; nf++)
#pragma unroll
                for (int c = 0; c < 4; c++) s[nf][c] = 0.f;
#pragma unroll
            for (int kc = 0; kc < 4; kc++) {
                const uint32_t kswz = (uint32_t)(((2 * kc + bjbit) ^ lb) << 4);
#pragma unroll
                for (int np = 0; np < 4; np++) {
                    const int nf0 = 2 * np, nf1 = nf0 + 1;
                    uint32_t k0[2], k1[2];
                    ldsm_x2(k0[0], k0[1], stageB + kBase + nf0 * 1024 + kswz);
                    ldsm_x2(k1[0], k1[1], stageB + kBase + nf1 * 1024 + kswz);
                    mma_f16(s[nf0], qh[kc], k0);
                    mma_f16(s[nf1], qh[kc], k1);
                    mma_f16(s[nf0], ql[kc], k0);
                    mma_f16(s[nf1], ql[kc], k1);
                }
            }

            if (jt >= 2 * qi) {
                const int row0 = qbase + wid * 16 + gr, row1 = row0 + 8;
#pragma unroll
                for (int nf = 0; nf < 8; nf++) {
                    const int col = kvb + nf * 8 + 2 * tg;
                    if (col > row0)     s[nf][0] = -1e30f;
                    if (col + 1 > row0) s[nf][1] = -1e30f;
                    if (col > row1)     s[nf][2] = -1e30f;
                    if (col + 1 > row1) s[nf][3] = -1e30f;
                }
            }

            float rm0 = -1e30f, rm1 = -1e30f;
#pragma unroll
            for (int nf = 0; nf < 8; nf++) {
                rm0 = fmaxf(rm0, fmaxf(s[nf][0], s[nf][1]));
                rm1 = fmaxf(rm1, fmaxf(s[nf][2], s[nf][3]));
            }
            rm0 = fmaxf(rm0, __shfl_xor_sync(0xffffffffu, rm0, 1));
            rm0 = fmaxf(rm0, __shfl_xor_sync(0xffffffffu, rm0, 2));
            rm1 = fmaxf(rm1, __shfl_xor_sync(0xffffffffu, rm1, 1));
            rm1 = fmaxf(rm1, __shfl_xor_sync(0xffffffffu, rm1, 2));
            const float mn0 = fmaxf(m0, rm0), mn1 = fmaxf(m1, rm1);
            const float sc0 = exp2f(m0 - mn0), sc1 = exp2f(m1 - mn1);
            m0 = mn0; m1 = mn1;
#pragma unroll
            for (int nf = 0; nf < 8; nf++) {
                oacc[nf][0] *= sc0; oacc[nf][1] *= sc0;
                oacc[nf][2] *= sc1; oacc[nf][3] *= sc1;
            }
            lacc[0] *= sc0; lacc[1] *= sc0; lacc[2] *= sc1; lacc[3] *= sc1;

            // ---- P = exp2(s'-m') fp16; l += P·1; O += P V ----
#pragma unroll
            for (int kc = 0; kc < 4; kc++) {
                const uint32_t vswz = (uint32_t)(((2 * kc + bjbit) ^ lb) << 4);
                uint32_t pa[4];
                pa[0] = exp2_h2(s[2 * kc][0] - mn0,     s[2 * kc][1] - mn0);
                pa[1] = exp2_h2(s[2 * kc][2] - mn1,     s[2 * kc][3] - mn1);
                pa[2] = exp2_h2(s[2 * kc + 1][0] - mn0, s[2 * kc + 1][1] - mn0);
                pa[3] = exp2_h2(s[2 * kc + 1][2] - mn1, s[2 * kc + 1][3] - mn1);
                mma_f16(lacc, pa, bones);
#pragma unroll
                for (int np = 0; np < 4; np++) {
                    const int nf0 = 2 * np, nf1 = nf0 + 1;
                    uint32_t v0[2], v1[2];
                    ldsm_x2(v0[0], v0[1], stageB + vBase + nf0 * 1024 + vswz);
                    ldsm_x2(v1[0], v1[1], stageB + vBase + nf1 * 1024 + vswz);
                    mma_f16(oacc[nf0], pa, v0);
                    mma_f16(oacc[nf1], pa, v1);
                }
            }
        }

        stC += 2; if (stC >= 6) stC -= 6;
    }

    const float inv0 = 1.f / lacc[0], inv1 = 1.f / lacc[2];
    const int row0 = qbase + wid * 16 + gr;
#pragma unroll
    for (int nf = 0; nf < 8; nf++) {
        uint32_t h, l;
        split2(oacc[nf][0] * inv0, oacc[nf][1] * inv0, h, l);
        const int w = nf * 4 + tg;
        g_ah[wbase + (size_t)row0 * 32 + w] = h;
        g_al[wbase + (size_t)row0 * 32 + w] = l;
        split2(oacc[nf][2] * inv1, oacc[nf][3] * inv1, h, l);
        g_ah[wbase + (size_t)(row0 + 8) * 32 + w] = h;
        g_al[wbase + (size_t)(row0 + 8) * 32 + w] = l;
    }
}

// ---------------------------------------------------------------------------
extern "C" void kernel_launch(void* const* d_in, const int* in_sizes, int n_in,
                              void* d_out, int out_size)
{
    const float* X  = (const float*)d_in[0];
    const float* Wq = (const float*)d_in[1];
    const float* Wk = (const float*)d_in[2];
    const float* Wv = (const float*)d_in[3];
    const float* Wo = (const float*)d_in[4];
    const float* bo = (const float*)d_in[5];
    float* out = (float*)d_out;

    cudaFuncSetAttribute(qkv_kernel, cudaFuncAttributeMaxDynamicSharedMemorySize, GEMM_SMEM);
    cudaFuncSetAttribute(out_kernel, cudaFuncAttributeMaxDynamicSharedMemorySize, GEMM_SMEM);
    cudaFuncSetAttribute(attn_kernel, cudaFuncAttributeMaxDynamicSharedMemorySize, ATT_SMEM);

    const int total_words = MROWS * WPR + 4 * DMODEL * WPR;
    split_all_kernel<<<total_words / 256, 256>>>(X, Wq, Wk, Wv, Wo);
    qkv_kernel<<<dim3(DMODEL / 256, MROWS / 128, 3), 512, GEMM_SMEM>>>();
    vtrans_kernel<<<dim3(32, BHCNT), 256>>>();
    attn_kernel<<<dim3(16, BHCNT), 256, ATT_SMEM>>>();
    out_kernel<<<dim3(DMODEL / 256, MROWS / 128), 512, GEMM_SMEM>>>(bo, out);
}